// round 13
// baseline (speedup 1.0000x reference)
#include <cuda_runtime.h>
#include <cuda_fp16.h>

#define NN 50000
#define EDGES 1000000
#define DD 128
#define TOTE (EDGES + NN)

// ---------------- scratch ----------------
__device__ __half g_h16[2][NN * DD];   // per-branch transformed features
__device__ __half g_xin16[NN * DD];    // fp16 x_o
__device__ __half g_a16[2][NN * DD];   // per-branch fp16 x1
__device__ __half g_w16[4][DD * DD];   // fp16 weights: slot = layer*2 + branch
__device__ float g_ssrc[2 * NN];
__device__ float g_sdst[2 * NN];
__device__ unsigned g_gmax[8];
__device__ int   g_deg[2 * NN];        // zero at start; reset by k_csr each run
__device__ int   g_fill[2 * NN];
__device__ int   g_bsum[128];
__device__ int   g_sflag[128];         // look-back flags (zeroed in prep)
__device__ int   g_rowptr[2 * (NN + 1)];
__device__ int   g_col[2 * TOTE];

__device__ __forceinline__ unsigned encf(float f) {
    unsigned u = __float_as_uint(f);
    return (u & 0x80000000u) ? ~u : (u | 0x80000000u);
}
__device__ __forceinline__ float decf(unsigned u) {
    return __uint_as_float((u & 0x80000000u) ? (u & 0x7fffffffu) : ~u);
}
__device__ __forceinline__ float lrelu(float z) { return z > 0.f ? z : 0.2f * z; }

__device__ __forceinline__ void cp_async16(void* smem_dst, const void* gmem_src) {
    unsigned dst = (unsigned)__cvta_generic_to_shared(smem_dst);
    asm volatile("cp.async.cg.shared.global [%0], [%1], 16;" :: "r"(dst), "l"(gmem_src));
}
__device__ __forceinline__ void cp_async_commit_wait() {
    asm volatile("cp.async.commit_group;");
    asm volatile("cp.async.wait_group 0;");
}

// ---------------- merged: W fp16 conversion + inits + degree count (4 edges/thr) ----------------
#define WCONV_BLKS 64    // 4 matrices * 4096 float4 / 256
#define COUNT_BLKS ((2 * EDGES / 4 + 255) / 256)   // 1954
__global__ void k_prep_count(const float* __restrict__ W0, const float* __restrict__ W1,
                             const float* __restrict__ W2, const float* __restrict__ W3,
                             const int* __restrict__ ei_o,
                             const int* __restrict__ ei_s) {
    if (blockIdx.x < WCONV_BLKS) {
        int j = blockIdx.x * 256 + threadIdx.x;   // 0..16383
        int m = j >> 12;
        int q = j & 4095;
        const float* Wm = (m == 0) ? W0 : (m == 1) ? W1 : (m == 2) ? W2 : W3;
        float4 v = ((const float4*)Wm)[q];
        uint2 p;
        __half2 h0 = __floats2half2_rn(v.x, v.y);
        __half2 h1 = __floats2half2_rn(v.z, v.w);
        p.x = *(unsigned*)&h0;
        p.y = *(unsigned*)&h1;
        ((uint2*)g_w16[m])[q] = p;
        if (blockIdx.x == 0) {
            if (threadIdx.x < 8) g_gmax[threadIdx.x] = encf(-1e30f);
            if (threadIdx.x < 128) g_sflag[threadIdx.x] = 0;
        }
    } else {
        int t = (blockIdx.x - WCONV_BLKS) * 256 + threadIdx.x;
        int e0 = t * 4;
        if (e0 >= 2 * EDGES) return;
        int g = (e0 >= EDGES);
        int le = e0 - g * EDGES;
        const int* ei = g ? ei_s : ei_o;
        int* deg = g_deg + g * NN;
        if (le + 4 <= EDGES) {
            int4 d4 = *(const int4*)&ei[EDGES + le];
            atomicAdd(&deg[d4.x], 1);
            atomicAdd(&deg[d4.y], 1);
            atomicAdd(&deg[d4.z], 1);
            atomicAdd(&deg[d4.w], 1);
        } else {
            for (int q = 0; q < 4 && le + q < EDGES; ++q)
                atomicAdd(&deg[ei[EDGES + le + q]], 1);
        }
    }
}

// ---------------- CSR: scan + self-loop fill (decoupled look-back) ----------------
__global__ void k_csr() {
    __shared__ int wsum[32];
    __shared__ int s_boff;
    int tid = threadIdx.x;
    int lane = tid & 31;
    int wid = tid >> 5;
    int g = (blockIdx.x >= 49);
    int lb = blockIdx.x - g * 49;
    int idx = lb * 1024 + tid;
    int v = (idx < NN) ? (g_deg[g * NN + idx] + 1) : 0;   // +1 = self loop
    int sc = v;
#pragma unroll
    for (int off = 1; off < 32; off <<= 1) {
        int t = __shfl_up_sync(0xffffffffu, sc, off);
        if (lane >= off) sc += t;
    }
    if (lane == 31) wsum[wid] = sc;
    __syncthreads();
    if (wid == 0) {
        int ws = wsum[lane];
#pragma unroll
        for (int off = 1; off < 32; off <<= 1) {
            int t = __shfl_up_sync(0xffffffffu, ws, off);
            if (lane >= off) ws += t;
        }
        wsum[lane] = ws;
    }
    __syncthreads();
    int incl = sc + (wid ? wsum[wid - 1] : 0);
    int total = wsum[31];
    if (tid == 0) {
        g_bsum[g * 64 + lb] = total;
        __threadfence();
        *((volatile int*)&g_sflag[g * 64 + lb]) = 1;
    }
    if (wid == 0) {
        int acc = 0;
#pragma unroll
        for (int half = 0; half < 2; ++half) {
            int j = lane + half * 32;
            if (j < lb) {
                while (*((volatile int*)&g_sflag[g * 64 + j]) == 0) { }
                acc += *((volatile int*)&g_bsum[g * 64 + j]);
            }
        }
#pragma unroll
        for (int off = 16; off; off >>= 1)
            acc += __shfl_xor_sync(0xffffffffu, acc, off);
        if (lane == 0) s_boff = acc;
    }
    __syncthreads();
    int boff = s_boff;
    if (idx < NN) {
        int p = incl - v + boff;
        g_rowptr[g * (NN + 1) + idx] = p;
        g_col[g * TOTE + p] = idx;
        g_fill[g * NN + idx] = p + 1;
        g_deg[g * NN + idx] = 0;      // reset for next replay
    }
    if (idx == 0) g_rowptr[g * (NN + 1) + NN] = TOTE;
}

// ---------------- merged: x->fp16 conversion + edge fill (compatible footprints) ----------------
#define XCONV_BLKS 6250   // NN*DD/4 float4 / 256
__global__ __launch_bounds__(256) void k_fill_conv(const float* __restrict__ x,
                                                   const int* __restrict__ ei_o,
                                                   const int* __restrict__ ei_s) {
    if (blockIdx.x < XCONV_BLKS) {
        int i = blockIdx.x * 256 + threadIdx.x;
        float4 v = ((const float4*)x)[i];
        uint2 p;
        __half2 h0 = __floats2half2_rn(v.x, v.y);
        __half2 h1 = __floats2half2_rn(v.z, v.w);
        p.x = *(unsigned*)&h0;
        p.y = *(unsigned*)&h1;
        ((uint2*)g_xin16)[i] = p;
    } else {
        int t = (blockIdx.x - XCONV_BLKS) * 256 + threadIdx.x;
        int e0 = t * 4;
        if (e0 >= 2 * EDGES) return;
        int g = (e0 >= EDGES);
        int le = e0 - g * EDGES;
        const int* ei = g ? ei_s : ei_o;
        int* fill = g_fill + g * NN;
        int* col = g_col + g * TOTE;
        if (le + 4 <= EDGES) {
            int4 s4 = *(const int4*)&ei[le];
            int4 d4 = *(const int4*)&ei[EDGES + le];
            int p0 = atomicAdd(&fill[d4.x], 1);
            int p1 = atomicAdd(&fill[d4.y], 1);
            int p2 = atomicAdd(&fill[d4.z], 1);
            int p3 = atomicAdd(&fill[d4.w], 1);
            col[p0] = s4.x; col[p1] = s4.y; col[p2] = s4.z; col[p3] = s4.w;
        } else {
            for (int q = 0; q < 4 && le + q < EDGES; ++q) {
                int s = ei[le + q];
                int d = ei[EDGES + le + q];
                int pos = atomicAdd(&fill[d], 1);
                col[pos] = s;
            }
        }
    }
}

// ---------------- HMMA GEMM: M=128 tile, K=128 single-stage, cp.async loads ----------------
#define SPITCH 136

__device__ __forceinline__ void ldsm_x4(unsigned& r0, unsigned& r1, unsigned& r2, unsigned& r3,
                                        unsigned addr) {
    asm volatile("ldmatrix.sync.aligned.m8n8.x4.shared.b16 {%0,%1,%2,%3}, [%4];"
                 : "=r"(r0), "=r"(r1), "=r"(r2), "=r"(r3) : "r"(addr));
}
__device__ __forceinline__ void ldsm_x4_t(unsigned& r0, unsigned& r1, unsigned& r2, unsigned& r3,
                                          unsigned addr) {
    asm volatile("ldmatrix.sync.aligned.m8n8.x4.trans.shared.b16 {%0,%1,%2,%3}, [%4];"
                 : "=r"(r0), "=r"(r1), "=r"(r2), "=r"(r3) : "r"(addr));
}
__device__ __forceinline__ void hmma(float* d, unsigned a0, unsigned a1, unsigned a2, unsigned a3,
                                     unsigned b0, unsigned b1) {
    asm volatile("mma.sync.aligned.m16n8k16.row.col.f32.f16.f16.f32 "
                 "{%0,%1,%2,%3}, {%4,%5,%6,%7}, {%8,%9}, {%0,%1,%2,%3};"
                 : "+f"(d[0]), "+f"(d[1]), "+f"(d[2]), "+f"(d[3])
                 : "r"(a0), "r"(a1), "r"(a2), "r"(a3), "r"(b0), "r"(b1));
}

#define GEMM_TILES 392          // ceil(NN/128)
#define GEMM_SMEM (2 * 128 * SPITCH * 2)   // 69632 bytes

__global__ __launch_bounds__(256, 2) void k_gemm(
    int layer,
    const float* __restrict__ as0, const float* __restrict__ as1,
    const float* __restrict__ ad0, const float* __restrict__ ad1)
{
    int b = blockIdx.y;
    const __half* __restrict__ A = (layer == 0) ? g_xin16 : g_a16[b];
    int slot = layer * 2 + b;
    const __half* __restrict__ Wh = g_w16[slot];
    const float* __restrict__ a_src = b ? as1 : as0;
    const float* __restrict__ a_dst = b ? ad1 : ad0;
    __half* __restrict__ H = g_h16[b];
    float* __restrict__ ssrc = g_ssrc + b * NN;
    float* __restrict__ sdst = g_sdst + b * NN;

    extern __shared__ __half sh[];
    __half* Ash = sh;
    __half* Bsh = sh + 128 * SPITCH;
    __shared__ float s_red[8][2];
    int tid = threadIdx.x;
    int l = tid & 31;
    int wid = tid >> 5;
    int row0 = blockIdx.x * 128;

    // B tile: cp.async straight copy of fp16 W
#pragma unroll
    for (int t = 0; t < 8; ++t) {
        int i = t * 256 + tid;
        int r = i >> 4;
        int c = i & 15;
        cp_async16(&Bsh[r * SPITCH + c * 8], &Wh[r * DD + c * 8]);
    }
    // A tile: cp.async fp16
#pragma unroll
    for (int t = 0; t < 8; ++t) {
        int i = t * 256 + tid;
        int r = i >> 4;
        int c = i & 15;
        if (row0 + r < NN)
            cp_async16(&Ash[r * SPITCH + c * 8], &A[(row0 + r) * DD + c * 8]);
        else
            *(uint4*)&Ash[r * SPITCH + c * 8] = make_uint4(0u, 0u, 0u, 0u);
    }
    cp_async_commit_wait();
    __syncthreads();

    float acc[16][4];
#pragma unroll
    for (int j = 0; j < 16; ++j)
#pragma unroll
        for (int q = 0; q < 4; ++q) acc[j][q] = 0.f;

    int arow = wid * 16 + (l & 15);
    int acolo = (l >> 4) * 8;
    unsigned a_base = (unsigned)__cvta_generic_to_shared(&Ash[arow * SPITCH + acolo]);
    int brow = l & 15;
    int bcolo = (l >> 4) * 8;
    unsigned b_base = (unsigned)__cvta_generic_to_shared(&Bsh[brow * SPITCH + bcolo]);

#pragma unroll
    for (int ks = 0; ks < 8; ++ks) {
        unsigned a0, a1, a2, a3;
        ldsm_x4(a0, a1, a2, a3, a_base + (unsigned)(ks * 16 * 2));
#pragma unroll
        for (int np = 0; np < 8; ++np) {
            unsigned b0, b1, b2, b3;
            ldsm_x4_t(b0, b1, b2, b3,
                      b_base + (unsigned)((ks * 16 * SPITCH + np * 16) * 2));
            hmma(acc[2 * np], a0, a1, a2, a3, b0, b1);
            hmma(acc[2 * np + 1], a0, a1, a2, a3, b2, b3);
        }
    }

    // epilogue: write h fp16, fused s_src/s_dst
    int g = l >> 2, tg = l & 3;
    int r0g = row0 + wid * 16 + g;
    int r1g = r0g + 8;
    float ps0 = 0.f, pd0 = 0.f, ps1 = 0.f, pd1 = 0.f;
#pragma unroll
    for (int j = 0; j < 16; ++j) {
        int colc = j * 8 + tg * 2;
        float2 asv = *(const float2*)&a_src[colc];
        float2 adv = *(const float2*)&a_dst[colc];
        ps0 += acc[j][0] * asv.x + acc[j][1] * asv.y;
        pd0 += acc[j][0] * adv.x + acc[j][1] * adv.y;
        ps1 += acc[j][2] * asv.x + acc[j][3] * asv.y;
        pd1 += acc[j][2] * adv.x + acc[j][3] * adv.y;
        if (r0g < NN)
            *(__half2*)&H[r0g * DD + colc] = __floats2half2_rn(acc[j][0], acc[j][1]);
        if (r1g < NN)
            *(__half2*)&H[r1g * DD + colc] = __floats2half2_rn(acc[j][2], acc[j][3]);
    }
#pragma unroll
    for (int off = 1; off < 4; off <<= 1) {
        ps0 += __shfl_xor_sync(0xffffffffu, ps0, off);
        pd0 += __shfl_xor_sync(0xffffffffu, pd0, off);
        ps1 += __shfl_xor_sync(0xffffffffu, ps1, off);
        pd1 += __shfl_xor_sync(0xffffffffu, pd1, off);
    }
    float lms = -1e30f, lmd = -1e30f;
    if (tg == 0) {
        if (r0g < NN) {
            ssrc[r0g] = ps0; sdst[r0g] = pd0;
            lms = ps0; lmd = pd0;
        }
        if (r1g < NN) {
            ssrc[r1g] = ps1; sdst[r1g] = pd1;
            lms = fmaxf(lms, ps1); lmd = fmaxf(lmd, pd1);
        }
    }
#pragma unroll
    for (int off = 16; off; off >>= 1) {
        lms = fmaxf(lms, __shfl_xor_sync(0xffffffffu, lms, off));
        lmd = fmaxf(lmd, __shfl_xor_sync(0xffffffffu, lmd, off));
    }
    if (l == 0) { s_red[wid][0] = lms; s_red[wid][1] = lmd; }
    __syncthreads();
    if (tid == 0) {
        float ms = s_red[0][0], md = s_red[0][1];
#pragma unroll
        for (int i = 1; i < 8; ++i) {
            ms = fmaxf(ms, s_red[i][0]);
            md = fmaxf(md, s_red[i][1]);
        }
        atomicMax(&g_gmax[2 * slot], encf(ms));
        atomicMax(&g_gmax[2 * slot + 1], encf(md));
    }
}

// ---------------- shared edge-softmax accumulate (warp-per-dst) ----------------
__device__ __forceinline__ void agg_row(const int* __restrict__ col,
                                        const float* __restrict__ ss,
                                        const uint2* __restrict__ h2,
                                        int beg, int end, int l,
                                        float sd, float c,
                                        float4& acc, float& den) {
    int e = beg;
    for (; e + 8 <= end; e += 8) {
        int s[8];
        float wt[8];
#pragma unroll
        for (int q = 0; q < 8; ++q) s[q] = col[e + q];
#pragma unroll
        for (int q = 0; q < 8; ++q) wt[q] = __expf(lrelu(ss[s[q]] + sd) - c);
#pragma unroll
        for (int q = 0; q < 8; ++q) {
            uint2 r = h2[s[q] * 32 + l];
            float2 a = __half22float2(*(__half2*)&r.x);
            float2 b = __half22float2(*(__half2*)&r.y);
            den += wt[q];
            acc.x += wt[q] * a.x; acc.y += wt[q] * a.y;
            acc.z += wt[q] * b.x; acc.w += wt[q] * b.y;
        }
    }
    for (; e < end; ++e) {
        int s = col[e];
        float wgt = __expf(lrelu(ss[s] + sd) - c);
        uint2 r = h2[s * 32 + l];
        float2 a = __half22float2(*(__half2*)&r.x);
        float2 b = __half22float2(*(__half2*)&r.y);
        den += wgt;
        acc.x += wgt * a.x; acc.y += wgt * a.y;
        acc.z += wgt * b.x; acc.w += wgt * b.y;
    }
}

// ---------------- layer-1 aggregate (both branches via grid.y) ----------------
__global__ __launch_bounds__(256) void k_aggregate1(const float* __restrict__ bias0,
                                                    const float* __restrict__ bias1) {
    int b = blockIdx.y;
    const int* __restrict__ rowptr = g_rowptr + b * (NN + 1);
    const int* __restrict__ col    = g_col + b * TOTE;
    const float* __restrict__ bias = b ? bias1 : bias0;
    int w = (blockIdx.x * blockDim.x + threadIdx.x) >> 5;
    int l = threadIdx.x & 31;
    if (w >= NN) return;
    float c = lrelu(decf(g_gmax[2 * b]) + decf(g_gmax[2 * b + 1]));
    float sd = g_sdst[b * NN + w];
    float4 acc = make_float4(0.f, 0.f, 0.f, 0.f);
    float den = 0.f;
    agg_row(col, g_ssrc + b * NN, (const uint2*)g_h16[b],
            rowptr[w], rowptr[w + 1], l, sd, c, acc, den);
    float inv = 1.f / (den + 1e-16f);
    float2 bv0 = ((const float2*)bias)[2 * l];
    float2 bv1 = ((const float2*)bias)[2 * l + 1];
    float4 o;
    o.x = fmaxf(acc.x * inv + bv0.x, 0.f);
    o.y = fmaxf(acc.y * inv + bv0.y, 0.f);
    o.z = fmaxf(acc.z * inv + bv1.x, 0.f);
    o.w = fmaxf(acc.w * inv + bv1.y, 0.f);
    __half2 h0 = __floats2half2_rn(o.x, o.y);
    __half2 h1 = __floats2half2_rn(o.z, o.w);
    uint2 p;
    p.x = *(unsigned*)&h0;
    p.y = *(unsigned*)&h1;
    ((uint2*)g_a16[b])[w * 32 + l] = p;
}

// ---------------- layer-2 aggregate + fused pred head ----------------
__global__ __launch_bounds__(256) void k_agg2pred(const float* __restrict__ bias0,
                                                  const float* __restrict__ bias1,
                                                  const float* __restrict__ degree,
                                                  const float* __restrict__ Wp,
                                                  const float* __restrict__ bp,
                                                  float* __restrict__ out) {
    int w = (blockIdx.x * blockDim.x + threadIdx.x) >> 5;
    int l = threadIdx.x & 31;
    if (w >= NN) return;
    float4 xb[2];
#pragma unroll
    for (int b = 0; b < 2; ++b) {
        const int* __restrict__ rowptr = g_rowptr + b * (NN + 1);
        const int* __restrict__ col    = g_col + b * TOTE;
        const float* __restrict__ bias = b ? bias1 : bias0;
        float c = lrelu(decf(g_gmax[4 + 2 * b]) + decf(g_gmax[4 + 2 * b + 1]));
        float sd = g_sdst[b * NN + w];
        float4 acc = make_float4(0.f, 0.f, 0.f, 0.f);
        float den = 0.f;
        agg_row(col, g_ssrc + b * NN, (const uint2*)g_h16[b],
                rowptr[w], rowptr[w + 1], l, sd, c, acc, den);
        float inv = 1.f / (den + 1e-16f);
        float2 bv0 = ((const float2*)bias)[2 * l];
        float2 bv1 = ((const float2*)bias)[2 * l + 1];
        xb[b].x = acc.x * inv + bv0.x;
        xb[b].y = acc.y * inv + bv0.y;
        xb[b].z = acc.z * inv + bv1.x;
        xb[b].w = acc.w * inv + bv1.y;
    }
    float4 xo = xb[0], xs = xb[1];
    float dg = degree[w * 32 + l];
    int k0 = l * 4;
    float z0 = xo.x * Wp[(k0 + 0) * 2] + xo.y * Wp[(k0 + 1) * 2]
             + xo.z * Wp[(k0 + 2) * 2] + xo.w * Wp[(k0 + 3) * 2]
             + xs.x * Wp[(128 + k0 + 0) * 2] + xs.y * Wp[(128 + k0 + 1) * 2]
             + xs.z * Wp[(128 + k0 + 2) * 2] + xs.w * Wp[(128 + k0 + 3) * 2]
             + dg * Wp[(256 + l) * 2];
    float z1 = xo.x * Wp[(k0 + 0) * 2 + 1] + xo.y * Wp[(k0 + 1) * 2 + 1]
             + xo.z * Wp[(k0 + 2) * 2 + 1] + xo.w * Wp[(k0 + 3) * 2 + 1]
             + xs.x * Wp[(128 + k0 + 0) * 2 + 1] + xs.y * Wp[(128 + k0 + 1) * 2 + 1]
             + xs.z * Wp[(128 + k0 + 2) * 2 + 1] + xs.w * Wp[(128 + k0 + 3) * 2 + 1]
             + dg * Wp[(256 + l) * 2 + 1];
#pragma unroll
    for (int off = 16; off; off >>= 1) {
        z0 += __shfl_xor_sync(0xffffffffu, z0, off);
        z1 += __shfl_xor_sync(0xffffffffu, z1, off);
    }
    z0 += bp[0];
    z1 += bp[1];
    float mz = fmaxf(z0, z1);
    float e0 = __expf(z0 - mz), e1 = __expf(z1 - mz);
    float inv = 1.f / (e0 + e1);
    float a0 = e0 * inv, a1 = e1 * inv;
    float4 o;
    o.x = a0 * xo.x + a1 * xs.x;
    o.y = a0 * xo.y + a1 * xs.y;
    o.z = a0 * xo.z + a1 * xs.z;
    o.w = a0 * xo.w + a1 * xs.w;
    ((float4*)out)[w * 32 + l] = o;
}

extern "C" void kernel_launch(void* const* d_in, const int* in_sizes, int n_in,
                              void* d_out, int out_size) {
    const float* x_o    = (const float*)d_in[0];
    const float* degree = (const float*)d_in[1];
    const int *ei_o, *ei_s;
    int base;
    if (in_sizes[2] == 2 * EDGES) {
        ei_o = (const int*)d_in[2];
        ei_s = (const int*)d_in[3];
        base = 4;
    } else {
        base = 2;
        ei_o = (const int*)d_in[20];
        ei_s = (const int*)d_in[21];
    }
    const float* W_o1 = (const float*)d_in[base + 0];
    const float* a_src_o1 = (const float*)d_in[base + 1];
    const float* a_dst_o1 = (const float*)d_in[base + 2];
    const float* b_o1 = (const float*)d_in[base + 3];
    const float* W_o2 = (const float*)d_in[base + 4];
    const float* a_src_o2 = (const float*)d_in[base + 5];
    const float* a_dst_o2 = (const float*)d_in[base + 6];
    const float* b_o2 = (const float*)d_in[base + 7];
    const float* W_s1 = (const float*)d_in[base + 8];
    const float* a_src_s1 = (const float*)d_in[base + 9];
    const float* a_dst_s1 = (const float*)d_in[base + 10];
    const float* b_s1 = (const float*)d_in[base + 11];
    const float* W_s2 = (const float*)d_in[base + 12];
    const float* a_src_s2 = (const float*)d_in[base + 13];
    const float* a_dst_s2 = (const float*)d_in[base + 14];
    const float* b_s2 = (const float*)d_in[base + 15];
    const float* W_pred = (const float*)d_in[base + 16];
    const float* b_pred = (const float*)d_in[base + 17];
    float* out = (float*)d_out;

    cudaFuncSetAttribute(k_gemm, cudaFuncAttributeMaxDynamicSharedMemorySize, GEMM_SMEM);

    k_prep_count<<<WCONV_BLKS + COUNT_BLKS, 256>>>(W_o1, W_s1, W_o2, W_s2, ei_o, ei_s);
    k_csr<<<98, 1024>>>();
    k_fill_conv<<<XCONV_BLKS + COUNT_BLKS, 256>>>(x_o, ei_o, ei_s);
    k_gemm<<<dim3(GEMM_TILES, 2), 256, GEMM_SMEM>>>(0, a_src_o1, a_src_s1, a_dst_o1, a_dst_s1);
    k_aggregate1<<<dim3(NN / 8, 2), 256>>>(b_o1, b_s1);
    k_gemm<<<dim3(GEMM_TILES, 2), 256, GEMM_SMEM>>>(1, a_src_o2, a_src_s2, a_dst_o2, a_dst_s2);
    k_agg2pred<<<NN / 8, 256>>>(b_o2, b_s2, degree, W_pred, b_pred, out);
}

// round 14
// speedup vs baseline: 1.0160x; 1.0160x over previous
#include <cuda_runtime.h>
#include <cuda_fp16.h>

#define NN 50000
#define EDGES 1000000
#define DD 128
#define TOTE (EDGES + NN)

// ---------------- scratch ----------------
__device__ __half g_h16[2][NN * DD];   // per-branch transformed features
__device__ __half g_xin16[NN * DD];    // fp16 x_o
__device__ __half g_a16[2][NN * DD];   // per-branch fp16 x1
__device__ __half g_w16[4][DD * DD];   // fp16 weights: slot = layer*2 + branch
__device__ float g_ssrc[2 * NN];
__device__ float g_sdst[2 * NN];
__device__ unsigned g_gmax[8];
__device__ int   g_deg[2 * NN];        // zero at start; reset by k_csr each run
__device__ int   g_fill[2 * NN];
__device__ int   g_bsum[128];
__device__ int   g_sflag[128];         // look-back flags (zeroed in prep)
__device__ int   g_rowptr[2 * (NN + 1)];
__device__ int   g_col[2 * TOTE];

__device__ __forceinline__ unsigned encf(float f) {
    unsigned u = __float_as_uint(f);
    return (u & 0x80000000u) ? ~u : (u | 0x80000000u);
}
__device__ __forceinline__ float decf(unsigned u) {
    return __uint_as_float((u & 0x80000000u) ? (u & 0x7fffffffu) : ~u);
}
__device__ __forceinline__ float lrelu(float z) { return z > 0.f ? z : 0.2f * z; }

__device__ __forceinline__ void cp_async16(void* smem_dst, const void* gmem_src) {
    unsigned dst = (unsigned)__cvta_generic_to_shared(smem_dst);
    asm volatile("cp.async.cg.shared.global [%0], [%1], 16;" :: "r"(dst), "l"(gmem_src));
}
__device__ __forceinline__ void cp_async_commit_wait() {
    asm volatile("cp.async.commit_group;");
    asm volatile("cp.async.wait_group 0;");
}

// ---------------- merged: W fp16 conversion + inits + degree count (4 edges/thr) ----------------
#define WCONV_BLKS 64    // 4 matrices * 4096 float4 / 256
#define COUNT_BLKS ((2 * EDGES / 4 + 255) / 256)   // 1954
__global__ void k_prep_count(const float* __restrict__ W0, const float* __restrict__ W1,
                             const float* __restrict__ W2, const float* __restrict__ W3,
                             const int* __restrict__ ei_o,
                             const int* __restrict__ ei_s) {
    if (blockIdx.x < WCONV_BLKS) {
        int j = blockIdx.x * 256 + threadIdx.x;   // 0..16383
        int m = j >> 12;
        int q = j & 4095;
        const float* Wm = (m == 0) ? W0 : (m == 1) ? W1 : (m == 2) ? W2 : W3;
        float4 v = ((const float4*)Wm)[q];
        uint2 p;
        __half2 h0 = __floats2half2_rn(v.x, v.y);
        __half2 h1 = __floats2half2_rn(v.z, v.w);
        p.x = *(unsigned*)&h0;
        p.y = *(unsigned*)&h1;
        ((uint2*)g_w16[m])[q] = p;
        if (blockIdx.x == 0) {
            if (threadIdx.x < 8) g_gmax[threadIdx.x] = encf(-1e30f);
            if (threadIdx.x < 128) g_sflag[threadIdx.x] = 0;
        }
    } else {
        int t = (blockIdx.x - WCONV_BLKS) * 256 + threadIdx.x;
        int e0 = t * 4;
        if (e0 >= 2 * EDGES) return;
        int g = (e0 >= EDGES);
        int le = e0 - g * EDGES;
        const int* ei = g ? ei_s : ei_o;
        int* deg = g_deg + g * NN;
        if (le + 4 <= EDGES) {
            int4 d4 = *(const int4*)&ei[EDGES + le];
            atomicAdd(&deg[d4.x], 1);
            atomicAdd(&deg[d4.y], 1);
            atomicAdd(&deg[d4.z], 1);
            atomicAdd(&deg[d4.w], 1);
        } else {
            for (int q = 0; q < 4 && le + q < EDGES; ++q)
                atomicAdd(&deg[ei[EDGES + le + q]], 1);
        }
    }
}

// ---------------- CSR: scan + self-loop fill (decoupled look-back) ----------------
__global__ void k_csr() {
    __shared__ int wsum[32];
    __shared__ int s_boff;
    int tid = threadIdx.x;
    int lane = tid & 31;
    int wid = tid >> 5;
    int g = (blockIdx.x >= 49);
    int lb = blockIdx.x - g * 49;
    int idx = lb * 1024 + tid;
    int v = (idx < NN) ? (g_deg[g * NN + idx] + 1) : 0;   // +1 = self loop
    int sc = v;
#pragma unroll
    for (int off = 1; off < 32; off <<= 1) {
        int t = __shfl_up_sync(0xffffffffu, sc, off);
        if (lane >= off) sc += t;
    }
    if (lane == 31) wsum[wid] = sc;
    __syncthreads();
    if (wid == 0) {
        int ws = wsum[lane];
#pragma unroll
        for (int off = 1; off < 32; off <<= 1) {
            int t = __shfl_up_sync(0xffffffffu, ws, off);
            if (lane >= off) ws += t;
        }
        wsum[lane] = ws;
    }
    __syncthreads();
    int incl = sc + (wid ? wsum[wid - 1] : 0);
    int total = wsum[31];
    if (tid == 0) {
        g_bsum[g * 64 + lb] = total;
        __threadfence();
        *((volatile int*)&g_sflag[g * 64 + lb]) = 1;
    }
    if (wid == 0) {
        int acc = 0;
#pragma unroll
        for (int half = 0; half < 2; ++half) {
            int j = lane + half * 32;
            if (j < lb) {
                while (*((volatile int*)&g_sflag[g * 64 + j]) == 0) { }
                acc += *((volatile int*)&g_bsum[g * 64 + j]);
            }
        }
#pragma unroll
        for (int off = 16; off; off >>= 1)
            acc += __shfl_xor_sync(0xffffffffu, acc, off);
        if (lane == 0) s_boff = acc;
    }
    __syncthreads();
    int boff = s_boff;
    if (idx < NN) {
        int p = incl - v + boff;
        g_rowptr[g * (NN + 1) + idx] = p;
        g_col[g * TOTE + p] = idx;
        g_fill[g * NN + idx] = p + 1;
        g_deg[g * NN + idx] = 0;      // reset for next replay
    }
    if (idx == 0) g_rowptr[g * (NN + 1) + NN] = TOTE;
}

// ---------------- merged: edge fill FIRST, then x->fp16 conversion ----------------
#define XCONV_BLKS 6250   // NN*DD/4 float4 / 256
__global__ __launch_bounds__(256) void k_fill_conv(const float* __restrict__ x,
                                                   const int* __restrict__ ei_o,
                                                   const int* __restrict__ ei_s) {
    if (blockIdx.x < COUNT_BLKS) {
        // fill blocks dispatched first: atomic scatter starts immediately
        int t = blockIdx.x * 256 + threadIdx.x;
        int e0 = t * 4;
        if (e0 >= 2 * EDGES) return;
        int g = (e0 >= EDGES);
        int le = e0 - g * EDGES;
        const int* ei = g ? ei_s : ei_o;
        int* fill = g_fill + g * NN;
        int* col = g_col + g * TOTE;
        if (le + 4 <= EDGES) {
            int4 s4 = *(const int4*)&ei[le];
            int4 d4 = *(const int4*)&ei[EDGES + le];
            int p0 = atomicAdd(&fill[d4.x], 1);
            int p1 = atomicAdd(&fill[d4.y], 1);
            int p2 = atomicAdd(&fill[d4.z], 1);
            int p3 = atomicAdd(&fill[d4.w], 1);
            col[p0] = s4.x; col[p1] = s4.y; col[p2] = s4.z; col[p3] = s4.w;
        } else {
            for (int q = 0; q < 4 && le + q < EDGES; ++q) {
                int s = ei[le + q];
                int d = ei[EDGES + le + q];
                int pos = atomicAdd(&fill[d], 1);
                col[pos] = s;
            }
        }
    } else {
        int i = (blockIdx.x - COUNT_BLKS) * 256 + threadIdx.x;
        float4 v = ((const float4*)x)[i];
        uint2 p;
        __half2 h0 = __floats2half2_rn(v.x, v.y);
        __half2 h1 = __floats2half2_rn(v.z, v.w);
        p.x = *(unsigned*)&h0;
        p.y = *(unsigned*)&h1;
        ((uint2*)g_xin16)[i] = p;
    }
}

// ---------------- HMMA GEMM: M=128 tile, K=128 single-stage, cp.async loads ----------------
#define SPITCH 136

__device__ __forceinline__ void ldsm_x4(unsigned& r0, unsigned& r1, unsigned& r2, unsigned& r3,
                                        unsigned addr) {
    asm volatile("ldmatrix.sync.aligned.m8n8.x4.shared.b16 {%0,%1,%2,%3}, [%4];"
                 : "=r"(r0), "=r"(r1), "=r"(r2), "=r"(r3) : "r"(addr));
}
__device__ __forceinline__ void ldsm_x4_t(unsigned& r0, unsigned& r1, unsigned& r2, unsigned& r3,
                                          unsigned addr) {
    asm volatile("ldmatrix.sync.aligned.m8n8.x4.trans.shared.b16 {%0,%1,%2,%3}, [%4];"
                 : "=r"(r0), "=r"(r1), "=r"(r2), "=r"(r3) : "r"(addr));
}
__device__ __forceinline__ void hmma(float* d, unsigned a0, unsigned a1, unsigned a2, unsigned a3,
                                     unsigned b0, unsigned b1) {
    asm volatile("mma.sync.aligned.m16n8k16.row.col.f32.f16.f16.f32 "
                 "{%0,%1,%2,%3}, {%4,%5,%6,%7}, {%8,%9}, {%0,%1,%2,%3};"
                 : "+f"(d[0]), "+f"(d[1]), "+f"(d[2]), "+f"(d[3])
                 : "r"(a0), "r"(a1), "r"(a2), "r"(a3), "r"(b0), "r"(b1));
}

#define GEMM_TILES 392          // ceil(NN/128)
#define GEMM_SMEM (2 * 128 * SPITCH * 2)   // 69632 bytes

__global__ __launch_bounds__(256, 2) void k_gemm(
    int layer,
    const float* __restrict__ as0, const float* __restrict__ as1,
    const float* __restrict__ ad0, const float* __restrict__ ad1)
{
    int b = blockIdx.y;
    const __half* __restrict__ A = (layer == 0) ? g_xin16 : g_a16[b];
    int slot = layer * 2 + b;
    const __half* __restrict__ Wh = g_w16[slot];
    const float* __restrict__ a_src = b ? as1 : as0;
    const float* __restrict__ a_dst = b ? ad1 : ad0;
    __half* __restrict__ H = g_h16[b];
    float* __restrict__ ssrc = g_ssrc + b * NN;
    float* __restrict__ sdst = g_sdst + b * NN;

    extern __shared__ __half sh[];
    __half* Ash = sh;
    __half* Bsh = sh + 128 * SPITCH;
    __shared__ float s_red[8][2];
    int tid = threadIdx.x;
    int l = tid & 31;
    int wid = tid >> 5;
    int row0 = blockIdx.x * 128;

#pragma unroll
    for (int t = 0; t < 8; ++t) {
        int i = t * 256 + tid;
        int r = i >> 4;
        int c = i & 15;
        cp_async16(&Bsh[r * SPITCH + c * 8], &Wh[r * DD + c * 8]);
    }
#pragma unroll
    for (int t = 0; t < 8; ++t) {
        int i = t * 256 + tid;
        int r = i >> 4;
        int c = i & 15;
        if (row0 + r < NN)
            cp_async16(&Ash[r * SPITCH + c * 8], &A[(row0 + r) * DD + c * 8]);
        else
            *(uint4*)&Ash[r * SPITCH + c * 8] = make_uint4(0u, 0u, 0u, 0u);
    }
    cp_async_commit_wait();
    __syncthreads();

    float acc[16][4];
#pragma unroll
    for (int j = 0; j < 16; ++j)
#pragma unroll
        for (int q = 0; q < 4; ++q) acc[j][q] = 0.f;

    int arow = wid * 16 + (l & 15);
    int acolo = (l >> 4) * 8;
    unsigned a_base = (unsigned)__cvta_generic_to_shared(&Ash[arow * SPITCH + acolo]);
    int brow = l & 15;
    int bcolo = (l >> 4) * 8;
    unsigned b_base = (unsigned)__cvta_generic_to_shared(&Bsh[brow * SPITCH + bcolo]);

#pragma unroll
    for (int ks = 0; ks < 8; ++ks) {
        unsigned a0, a1, a2, a3;
        ldsm_x4(a0, a1, a2, a3, a_base + (unsigned)(ks * 16 * 2));
#pragma unroll
        for (int np = 0; np < 8; ++np) {
            unsigned b0, b1, b2, b3;
            ldsm_x4_t(b0, b1, b2, b3,
                      b_base + (unsigned)((ks * 16 * SPITCH + np * 16) * 2));
            hmma(acc[2 * np], a0, a1, a2, a3, b0, b1);
            hmma(acc[2 * np + 1], a0, a1, a2, a3, b2, b3);
        }
    }

    // epilogue: write h fp16, fused s_src/s_dst
    int g = l >> 2, tg = l & 3;
    int r0g = row0 + wid * 16 + g;
    int r1g = r0g + 8;
    float ps0 = 0.f, pd0 = 0.f, ps1 = 0.f, pd1 = 0.f;
#pragma unroll
    for (int j = 0; j < 16; ++j) {
        int colc = j * 8 + tg * 2;
        float2 asv = *(const float2*)&a_src[colc];
        float2 adv = *(const float2*)&a_dst[colc];
        ps0 += acc[j][0] * asv.x + acc[j][1] * asv.y;
        pd0 += acc[j][0] * adv.x + acc[j][1] * adv.y;
        ps1 += acc[j][2] * asv.x + acc[j][3] * asv.y;
        pd1 += acc[j][2] * adv.x + acc[j][3] * adv.y;
        if (r0g < NN)
            *(__half2*)&H[r0g * DD + colc] = __floats2half2_rn(acc[j][0], acc[j][1]);
        if (r1g < NN)
            *(__half2*)&H[r1g * DD + colc] = __floats2half2_rn(acc[j][2], acc[j][3]);
    }
#pragma unroll
    for (int off = 1; off < 4; off <<= 1) {
        ps0 += __shfl_xor_sync(0xffffffffu, ps0, off);
        pd0 += __shfl_xor_sync(0xffffffffu, pd0, off);
        ps1 += __shfl_xor_sync(0xffffffffu, ps1, off);
        pd1 += __shfl_xor_sync(0xffffffffu, pd1, off);
    }
    float lms = -1e30f, lmd = -1e30f;
    if (tg == 0) {
        if (r0g < NN) {
            ssrc[r0g] = ps0; sdst[r0g] = pd0;
            lms = ps0; lmd = pd0;
        }
        if (r1g < NN) {
            ssrc[r1g] = ps1; sdst[r1g] = pd1;
            lms = fmaxf(lms, ps1); lmd = fmaxf(lmd, pd1);
        }
    }
#pragma unroll
    for (int off = 16; off; off >>= 1) {
        lms = fmaxf(lms, __shfl_xor_sync(0xffffffffu, lms, off));
        lmd = fmaxf(lmd, __shfl_xor_sync(0xffffffffu, lmd, off));
    }
    if (l == 0) { s_red[wid][0] = lms; s_red[wid][1] = lmd; }
    __syncthreads();
    if (tid == 0) {
        float ms = s_red[0][0], md = s_red[0][1];
#pragma unroll
        for (int i = 1; i < 8; ++i) {
            ms = fmaxf(ms, s_red[i][0]);
            md = fmaxf(md, s_red[i][1]);
        }
        atomicMax(&g_gmax[2 * slot], encf(ms));
        atomicMax(&g_gmax[2 * slot + 1], encf(md));
    }
}

// ---------------- shared edge-softmax accumulate (warp-per-dst) ----------------
__device__ __forceinline__ void agg_row(const int* __restrict__ col,
                                        const float* __restrict__ ss,
                                        const uint2* __restrict__ h2,
                                        int beg, int end, int l,
                                        float sd, float c,
                                        float4& acc, float& den) {
    int e = beg;
    for (; e + 8 <= end; e += 8) {
        int s[8];
        float wt[8];
#pragma unroll
        for (int q = 0; q < 8; ++q) s[q] = col[e + q];
#pragma unroll
        for (int q = 0; q < 8; ++q) wt[q] = __expf(lrelu(ss[s[q]] + sd) - c);
#pragma unroll
        for (int q = 0; q < 8; ++q) {
            uint2 r = h2[s[q] * 32 + l];
            float2 a = __half22float2(*(__half2*)&r.x);
            float2 b = __half22float2(*(__half2*)&r.y);
            den += wt[q];
            acc.x += wt[q] * a.x; acc.y += wt[q] * a.y;
            acc.z += wt[q] * b.x; acc.w += wt[q] * b.y;
        }
    }
    if (e + 4 <= end) {
        int s[4];
        float wt[4];
#pragma unroll
        for (int q = 0; q < 4; ++q) s[q] = col[e + q];
#pragma unroll
        for (int q = 0; q < 4; ++q) wt[q] = __expf(lrelu(ss[s[q]] + sd) - c);
#pragma unroll
        for (int q = 0; q < 4; ++q) {
            uint2 r = h2[s[q] * 32 + l];
            float2 a = __half22float2(*(__half2*)&r.x);
            float2 b = __half22float2(*(__half2*)&r.y);
            den += wt[q];
            acc.x += wt[q] * a.x; acc.y += wt[q] * a.y;
            acc.z += wt[q] * b.x; acc.w += wt[q] * b.y;
        }
        e += 4;
    }
    for (; e < end; ++e) {
        int s = col[e];
        float wgt = __expf(lrelu(ss[s] + sd) - c);
        uint2 r = h2[s * 32 + l];
        float2 a = __half22float2(*(__half2*)&r.x);
        float2 b = __half22float2(*(__half2*)&r.y);
        den += wgt;
        acc.x += wgt * a.x; acc.y += wgt * a.y;
        acc.z += wgt * b.x; acc.w += wgt * b.y;
    }
}

// ---------------- layer-1 aggregate (both branches via grid.y) ----------------
__global__ __launch_bounds__(256) void k_aggregate1(const float* __restrict__ bias0,
                                                    const float* __restrict__ bias1) {
    int b = blockIdx.y;
    const int* __restrict__ rowptr = g_rowptr + b * (NN + 1);
    const int* __restrict__ col    = g_col + b * TOTE;
    const float* __restrict__ bias = b ? bias1 : bias0;
    int w = (blockIdx.x * blockDim.x + threadIdx.x) >> 5;
    int l = threadIdx.x & 31;
    if (w >= NN) return;
    float c = lrelu(decf(g_gmax[2 * b]) + decf(g_gmax[2 * b + 1]));
    float sd = g_sdst[b * NN + w];
    int beg = __ldg(&rowptr[w]);
    int end = __ldg(&rowptr[w + 1]);
    float4 acc = make_float4(0.f, 0.f, 0.f, 0.f);
    float den = 0.f;
    agg_row(col, g_ssrc + b * NN, (const uint2*)g_h16[b], beg, end, l, sd, c, acc, den);
    float inv = 1.f / (den + 1e-16f);
    float2 bv0 = ((const float2*)bias)[2 * l];
    float2 bv1 = ((const float2*)bias)[2 * l + 1];
    float4 o;
    o.x = fmaxf(acc.x * inv + bv0.x, 0.f);
    o.y = fmaxf(acc.y * inv + bv0.y, 0.f);
    o.z = fmaxf(acc.z * inv + bv1.x, 0.f);
    o.w = fmaxf(acc.w * inv + bv1.y, 0.f);
    __half2 h0 = __floats2half2_rn(o.x, o.y);
    __half2 h1 = __floats2half2_rn(o.z, o.w);
    uint2 p;
    p.x = *(unsigned*)&h0;
    p.y = *(unsigned*)&h1;
    ((uint2*)g_a16[b])[w * 32 + l] = p;
}

// ---------------- layer-2 aggregate + fused pred head ----------------
__global__ __launch_bounds__(256) void k_agg2pred(const float* __restrict__ bias0,
                                                  const float* __restrict__ bias1,
                                                  const float* __restrict__ degree,
                                                  const float* __restrict__ Wp,
                                                  const float* __restrict__ bp,
                                                  float* __restrict__ out) {
    int w = (blockIdx.x * blockDim.x + threadIdx.x) >> 5;
    int l = threadIdx.x & 31;
    if (w >= NN) return;
    float4 xb[2];
#pragma unroll
    for (int b = 0; b < 2; ++b) {
        const int* __restrict__ rowptr = g_rowptr + b * (NN + 1);
        const int* __restrict__ col    = g_col + b * TOTE;
        const float* __restrict__ bias = b ? bias1 : bias0;
        float c = lrelu(decf(g_gmax[4 + 2 * b]) + decf(g_gmax[4 + 2 * b + 1]));
        float sd = g_sdst[b * NN + w];
        int beg = __ldg(&rowptr[w]);
        int end = __ldg(&rowptr[w + 1]);
        float4 acc = make_float4(0.f, 0.f, 0.f, 0.f);
        float den = 0.f;
        agg_row(col, g_ssrc + b * NN, (const uint2*)g_h16[b], beg, end, l, sd, c, acc, den);
        float inv = 1.f / (den + 1e-16f);
        float2 bv0 = ((const float2*)bias)[2 * l];
        float2 bv1 = ((const float2*)bias)[2 * l + 1];
        xb[b].x = acc.x * inv + bv0.x;
        xb[b].y = acc.y * inv + bv0.y;
        xb[b].z = acc.z * inv + bv1.x;
        xb[b].w = acc.w * inv + bv1.y;
    }
    float4 xo = xb[0], xs = xb[1];
    float dg = degree[w * 32 + l];
    int k0 = l * 4;
    float z0 = xo.x * Wp[(k0 + 0) * 2] + xo.y * Wp[(k0 + 1) * 2]
             + xo.z * Wp[(k0 + 2) * 2] + xo.w * Wp[(k0 + 3) * 2]
             + xs.x * Wp[(128 + k0 + 0) * 2] + xs.y * Wp[(128 + k0 + 1) * 2]
             + xs.z * Wp[(128 + k0 + 2) * 2] + xs.w * Wp[(128 + k0 + 3) * 2]
             + dg * Wp[(256 + l) * 2];
    float z1 = xo.x * Wp[(k0 + 0) * 2 + 1] + xo.y * Wp[(k0 + 1) * 2 + 1]
             + xo.z * Wp[(k0 + 2) * 2 + 1] + xo.w * Wp[(k0 + 3) * 2 + 1]
             + xs.x * Wp[(128 + k0 + 0) * 2 + 1] + xs.y * Wp[(128 + k0 + 1) * 2 + 1]
             + xs.z * Wp[(128 + k0 + 2) * 2 + 1] + xs.w * Wp[(128 + k0 + 3) * 2 + 1]
             + dg * Wp[(256 + l) * 2 + 1];
#pragma unroll
    for (int off = 16; off; off >>= 1) {
        z0 += __shfl_xor_sync(0xffffffffu, z0, off);
        z1 += __shfl_xor_sync(0xffffffffu, z1, off);
    }
    z0 += bp[0];
    z1 += bp[1];
    float mz = fmaxf(z0, z1);
    float e0 = __expf(z0 - mz), e1 = __expf(z1 - mz);
    float inv = 1.f / (e0 + e1);
    float a0 = e0 * inv, a1 = e1 * inv;
    float4 o;
    o.x = a0 * xo.x + a1 * xs.x;
    o.y = a0 * xo.y + a1 * xs.y;
    o.z = a0 * xo.z + a1 * xs.z;
    o.w = a0 * xo.w + a1 * xs.w;
    ((float4*)out)[w * 32 + l] = o;
}

extern "C" void kernel_launch(void* const* d_in, const int* in_sizes, int n_in,
                              void* d_out, int out_size) {
    const float* x_o    = (const float*)d_in[0];
    const float* degree = (const float*)d_in[1];
    const int *ei_o, *ei_s;
    int base;
    if (in_sizes[2] == 2 * EDGES) {
        ei_o = (const int*)d_in[2];
        ei_s = (const int*)d_in[3];
        base = 4;
    } else {
        base = 2;
        ei_o = (const int*)d_in[20];
        ei_s = (const int*)d_in[21];
    }
    const float* W_o1 = (const float*)d_in[base + 0];
    const float* a_src_o1 = (const float*)d_in[base + 1];
    const float* a_dst_o1 = (const float*)d_in[base + 2];
    const float* b_o1 = (const float*)d_in[base + 3];
    const float* W_o2 = (const float*)d_in[base + 4];
    const float* a_src_o2 = (const float*)d_in[base + 5];
    const float* a_dst_o2 = (const float*)d_in[base + 6];
    const float* b_o2 = (const float*)d_in[base + 7];
    const float* W_s1 = (const float*)d_in[base + 8];
    const float* a_src_s1 = (const float*)d_in[base + 9];
    const float* a_dst_s1 = (const float*)d_in[base + 10];
    const float* b_s1 = (const float*)d_in[base + 11];
    const float* W_s2 = (const float*)d_in[base + 12];
    const float* a_src_s2 = (const float*)d_in[base + 13];
    const float* a_dst_s2 = (const float*)d_in[base + 14];
    const float* b_s2 = (const float*)d_in[base + 15];
    const float* W_pred = (const float*)d_in[base + 16];
    const float* b_pred = (const float*)d_in[base + 17];
    float* out = (float*)d_out;

    cudaFuncSetAttribute(k_gemm, cudaFuncAttributeMaxDynamicSharedMemorySize, GEMM_SMEM);

    k_prep_count<<<WCONV_BLKS + COUNT_BLKS, 256>>>(W_o1, W_s1, W_o2, W_s2, ei_o, ei_s);
    k_csr<<<98, 1024>>>();
    k_fill_conv<<<COUNT_BLKS + XCONV_BLKS, 256>>>(x_o, ei_o, ei_s);
    k_gemm<<<dim3(GEMM_TILES, 2), 256, GEMM_SMEM>>>(0, a_src_o1, a_src_s1, a_dst_o1, a_dst_s1);
    k_aggregate1<<<dim3(NN / 8, 2), 256>>>(b_o1, b_s1);
    k_gemm<<<dim3(GEMM_TILES, 2), 256, GEMM_SMEM>>>(1, a_src_o2, a_src_s2, a_dst_o2, a_dst_s2);
    k_agg2pred<<<NN / 8, 256>>>(b_o2, b_s2, degree, W_pred, b_pred, out);
}

// round 15
// speedup vs baseline: 1.0184x; 1.0024x over previous
#include <cuda_runtime.h>
#include <cuda_fp16.h>

#define NN 50000
#define EDGES 1000000
#define DD 128
#define TOTE (EDGES + NN)

// ---------------- scratch ----------------
__device__ __half g_h16[2][NN * DD];   // per-branch transformed features
__device__ __half g_xin16[NN * DD];    // fp16 x_o
__device__ __half g_a16[2][NN * DD];   // per-branch fp16 x1
__device__ __half g_w16[4][DD * DD];   // fp16 weights: slot = layer*2 + branch
__device__ float g_ssrc[2 * NN];
__device__ float g_sdst[2 * NN];
__device__ unsigned g_gmax[8];
__device__ int   g_deg[2 * NN];        // zero at start; reset by k_csr each run
__device__ int   g_fill[2 * NN];
__device__ int   g_bsum[128];
__device__ int   g_sflag[128];         // look-back flags (zeroed in prep)
__device__ int   g_rowptr[2 * (NN + 1)];
__device__ int   g_col[2 * TOTE];

__device__ __forceinline__ unsigned encf(float f) {
    unsigned u = __float_as_uint(f);
    return (u & 0x80000000u) ? ~u : (u | 0x80000000u);
}
__device__ __forceinline__ float decf(unsigned u) {
    return __uint_as_float((u & 0x80000000u) ? (u & 0x7fffffffu) : ~u);
}
__device__ __forceinline__ float lrelu(float z) { return z > 0.f ? z : 0.2f * z; }

__device__ __forceinline__ void cp_async16(void* smem_dst, const void* gmem_src) {
    unsigned dst = (unsigned)__cvta_generic_to_shared(smem_dst);
    asm volatile("cp.async.cg.shared.global [%0], [%1], 16;" :: "r"(dst), "l"(gmem_src));
}

// ---------------- merged: W fp16 conversion + inits + degree count (4 edges/thr) ----------------
#define WCONV_BLKS 64    // 4 matrices * 4096 float4 / 256
#define COUNT_BLKS ((2 * EDGES / 4 + 255) / 256)   // 1954
__global__ void k_prep_count(const float* __restrict__ W0, const float* __restrict__ W1,
                             const float* __restrict__ W2, const float* __restrict__ W3,
                             const int* __restrict__ ei_o,
                             const int* __restrict__ ei_s) {
    if (blockIdx.x < WCONV_BLKS) {
        int j = blockIdx.x * 256 + threadIdx.x;   // 0..16383
        int m = j >> 12;
        int q = j & 4095;
        const float* Wm = (m == 0) ? W0 : (m == 1) ? W1 : (m == 2) ? W2 : W3;
        float4 v = ((const float4*)Wm)[q];
        uint2 p;
        __half2 h0 = __floats2half2_rn(v.x, v.y);
        __half2 h1 = __floats2half2_rn(v.z, v.w);
        p.x = *(unsigned*)&h0;
        p.y = *(unsigned*)&h1;
        ((uint2*)g_w16[m])[q] = p;
        if (blockIdx.x == 0) {
            if (threadIdx.x < 8) g_gmax[threadIdx.x] = encf(-1e30f);
            if (threadIdx.x < 128) g_sflag[threadIdx.x] = 0;
        }
    } else {
        int t = (blockIdx.x - WCONV_BLKS) * 256 + threadIdx.x;
        int e0 = t * 4;
        if (e0 >= 2 * EDGES) return;
        int g = (e0 >= EDGES);
        int le = e0 - g * EDGES;
        const int* ei = g ? ei_s : ei_o;
        int* deg = g_deg + g * NN;
        if (le + 4 <= EDGES) {
            int4 d4 = *(const int4*)&ei[EDGES + le];
            atomicAdd(&deg[d4.x], 1);
            atomicAdd(&deg[d4.y], 1);
            atomicAdd(&deg[d4.z], 1);
            atomicAdd(&deg[d4.w], 1);
        } else {
            for (int q = 0; q < 4 && le + q < EDGES; ++q)
                atomicAdd(&deg[ei[EDGES + le + q]], 1);
        }
    }
}

// ---------------- CSR: scan + self-loop fill (decoupled look-back) ----------------
__global__ void k_csr() {
    __shared__ int wsum[32];
    __shared__ int s_boff;
    int tid = threadIdx.x;
    int lane = tid & 31;
    int wid = tid >> 5;
    int g = (blockIdx.x >= 49);
    int lb = blockIdx.x - g * 49;
    int idx = lb * 1024 + tid;
    int v = (idx < NN) ? (g_deg[g * NN + idx] + 1) : 0;   // +1 = self loop
    int sc = v;
#pragma unroll
    for (int off = 1; off < 32; off <<= 1) {
        int t = __shfl_up_sync(0xffffffffu, sc, off);
        if (lane >= off) sc += t;
    }
    if (lane == 31) wsum[wid] = sc;
    __syncthreads();
    if (wid == 0) {
        int ws = wsum[lane];
#pragma unroll
        for (int off = 1; off < 32; off <<= 1) {
            int t = __shfl_up_sync(0xffffffffu, ws, off);
            if (lane >= off) ws += t;
        }
        wsum[lane] = ws;
    }
    __syncthreads();
    int incl = sc + (wid ? wsum[wid - 1] : 0);
    int total = wsum[31];
    if (tid == 0) {
        g_bsum[g * 64 + lb] = total;
        __threadfence();
        *((volatile int*)&g_sflag[g * 64 + lb]) = 1;
    }
    if (wid == 0) {
        int acc = 0;
#pragma unroll
        for (int half = 0; half < 2; ++half) {
            int j = lane + half * 32;
            if (j < lb) {
                while (*((volatile int*)&g_sflag[g * 64 + j]) == 0) { }
                acc += *((volatile int*)&g_bsum[g * 64 + j]);
            }
        }
#pragma unroll
        for (int off = 16; off; off >>= 1)
            acc += __shfl_xor_sync(0xffffffffu, acc, off);
        if (lane == 0) s_boff = acc;
    }
    __syncthreads();
    int boff = s_boff;
    if (idx < NN) {
        int p = incl - v + boff;
        g_rowptr[g * (NN + 1) + idx] = p;
        g_col[g * TOTE + p] = idx;
        g_fill[g * NN + idx] = p + 1;
        g_deg[g * NN + idx] = 0;      // reset for next replay
    }
    if (idx == 0) g_rowptr[g * (NN + 1) + NN] = TOTE;
}

// ---------------- merged: edge fill FIRST, then x->fp16 conversion ----------------
#define XCONV_BLKS 6250   // NN*DD/4 float4 / 256
__global__ __launch_bounds__(256) void k_fill_conv(const float* __restrict__ x,
                                                   const int* __restrict__ ei_o,
                                                   const int* __restrict__ ei_s) {
    if (blockIdx.x < COUNT_BLKS) {
        int t = blockIdx.x * 256 + threadIdx.x;
        int e0 = t * 4;
        if (e0 >= 2 * EDGES) return;
        int g = (e0 >= EDGES);
        int le = e0 - g * EDGES;
        const int* ei = g ? ei_s : ei_o;
        int* fill = g_fill + g * NN;
        int* col = g_col + g * TOTE;
        if (le + 4 <= EDGES) {
            int4 s4 = *(const int4*)&ei[le];
            int4 d4 = *(const int4*)&ei[EDGES + le];
            int p0 = atomicAdd(&fill[d4.x], 1);
            int p1 = atomicAdd(&fill[d4.y], 1);
            int p2 = atomicAdd(&fill[d4.z], 1);
            int p3 = atomicAdd(&fill[d4.w], 1);
            col[p0] = s4.x; col[p1] = s4.y; col[p2] = s4.z; col[p3] = s4.w;
        } else {
            for (int q = 0; q < 4 && le + q < EDGES; ++q) {
                int s = ei[le + q];
                int d = ei[EDGES + le + q];
                int pos = atomicAdd(&fill[d], 1);
                col[pos] = s;
            }
        }
    } else {
        int i = (blockIdx.x - COUNT_BLKS) * 256 + threadIdx.x;
        float4 v = ((const float4*)x)[i];
        uint2 p;
        __half2 h0 = __floats2half2_rn(v.x, v.y);
        __half2 h1 = __floats2half2_rn(v.z, v.w);
        p.x = *(unsigned*)&h0;
        p.y = *(unsigned*)&h1;
        ((uint2*)g_xin16)[i] = p;
    }
}

// ---------------- HMMA GEMM: M=128, 2-stage K pipeline (64 per stage) ----------------
#define APITCH 72    // halves per A-stage row (64 + 8 pad); 144B rows, 16B aligned
#define BPITCH 136   // halves per B-stage row (128 + 8 pad); 272B rows, 16B aligned
#define A_STAGE (128 * APITCH)     // halves
#define B_STAGE (64 * BPITCH)      // halves

__device__ __forceinline__ void ldsm_x4(unsigned& r0, unsigned& r1, unsigned& r2, unsigned& r3,
                                        unsigned addr) {
    asm volatile("ldmatrix.sync.aligned.m8n8.x4.shared.b16 {%0,%1,%2,%3}, [%4];"
                 : "=r"(r0), "=r"(r1), "=r"(r2), "=r"(r3) : "r"(addr));
}
__device__ __forceinline__ void ldsm_x4_t(unsigned& r0, unsigned& r1, unsigned& r2, unsigned& r3,
                                          unsigned addr) {
    asm volatile("ldmatrix.sync.aligned.m8n8.x4.trans.shared.b16 {%0,%1,%2,%3}, [%4];"
                 : "=r"(r0), "=r"(r1), "=r"(r2), "=r"(r3) : "r"(addr));
}
__device__ __forceinline__ void hmma(float* d, unsigned a0, unsigned a1, unsigned a2, unsigned a3,
                                     unsigned b0, unsigned b1) {
    asm volatile("mma.sync.aligned.m16n8k16.row.col.f32.f16.f16.f32 "
                 "{%0,%1,%2,%3}, {%4,%5,%6,%7}, {%8,%9}, {%0,%1,%2,%3};"
                 : "+f"(d[0]), "+f"(d[1]), "+f"(d[2]), "+f"(d[3])
                 : "r"(a0), "r"(a1), "r"(a2), "r"(a3), "r"(b0), "r"(b1));
}

#define GEMM_TILES 392          // ceil(NN/128)
#define GEMM_SMEM ((2 * A_STAGE + 2 * B_STAGE) * 2)   // 71680 bytes

__global__ __launch_bounds__(256, 2) void k_gemm(
    int layer,
    const float* __restrict__ as0, const float* __restrict__ as1,
    const float* __restrict__ ad0, const float* __restrict__ ad1)
{
    int b = blockIdx.y;
    const __half* __restrict__ A = (layer == 0) ? g_xin16 : g_a16[b];
    int slot = layer * 2 + b;
    const __half* __restrict__ Wh = g_w16[slot];
    const float* __restrict__ a_src = b ? as1 : as0;
    const float* __restrict__ a_dst = b ? ad1 : ad0;
    __half* __restrict__ H = g_h16[b];
    float* __restrict__ ssrc = g_ssrc + b * NN;
    float* __restrict__ sdst = g_sdst + b * NN;

    extern __shared__ __half sh[];
    __half* Ast[2] = { sh, sh + A_STAGE };
    __half* Bst[2] = { sh + 2 * A_STAGE, sh + 2 * A_STAGE + B_STAGE };
    __shared__ float s_red[8][2];
    int tid = threadIdx.x;
    int l = tid & 31;
    int wid = tid >> 5;
    int row0 = blockIdx.x * 128;

    // issue both stages' loads up-front, one commit group per stage
#pragma unroll
    for (int s = 0; s < 2; ++s) {
        // A stage: 128 rows x 64 halves = 1024 uint4, 4/thread
#pragma unroll
        for (int t = 0; t < 4; ++t) {
            int i = t * 256 + tid;
            int r = i >> 3;
            int c = i & 7;
            if (row0 + r < NN)
                cp_async16(&Ast[s][r * APITCH + c * 8], &A[(row0 + r) * DD + s * 64 + c * 8]);
            else
                *(uint4*)&Ast[s][r * APITCH + c * 8] = make_uint4(0u, 0u, 0u, 0u);
        }
        // B stage: 64 rows x 128 halves = 1024 uint4, 4/thread
#pragma unroll
        for (int t = 0; t < 4; ++t) {
            int i = t * 256 + tid;
            int r = i >> 4;
            int c = i & 15;
            cp_async16(&Bst[s][r * BPITCH + c * 8], &Wh[(s * 64 + r) * DD + c * 8]);
        }
        asm volatile("cp.async.commit_group;");
    }

    float acc[16][4];
#pragma unroll
    for (int j = 0; j < 16; ++j)
#pragma unroll
        for (int q = 0; q < 4; ++q) acc[j][q] = 0.f;

    int arow = wid * 16 + (l & 15);
    int acolo = (l >> 4) * 8;
    int brow = l & 15;
    int bcolo = (l >> 4) * 8;

#pragma unroll
    for (int s = 0; s < 2; ++s) {
        if (s == 0)
            asm volatile("cp.async.wait_group 1;");
        else
            asm volatile("cp.async.wait_group 0;");
        __syncthreads();
        unsigned a_base = (unsigned)__cvta_generic_to_shared(&Ast[s][arow * APITCH + acolo]);
        unsigned b_base = (unsigned)__cvta_generic_to_shared(&Bst[s][brow * BPITCH + bcolo]);
#pragma unroll
        for (int ks = 0; ks < 4; ++ks) {
            unsigned a0, a1, a2, a3;
            ldsm_x4(a0, a1, a2, a3, a_base + (unsigned)(ks * 16 * 2));
#pragma unroll
            for (int np = 0; np < 8; ++np) {
                unsigned b0, b1, b2, b3;
                ldsm_x4_t(b0, b1, b2, b3,
                          b_base + (unsigned)((ks * 16 * BPITCH + np * 16) * 2));
                hmma(acc[2 * np], a0, a1, a2, a3, b0, b1);
                hmma(acc[2 * np + 1], a0, a1, a2, a3, b2, b3);
            }
        }
    }

    // epilogue: write h fp16, fused s_src/s_dst
    int g = l >> 2, tg = l & 3;
    int r0g = row0 + wid * 16 + g;
    int r1g = r0g + 8;
    float ps0 = 0.f, pd0 = 0.f, ps1 = 0.f, pd1 = 0.f;
#pragma unroll
    for (int j = 0; j < 16; ++j) {
        int colc = j * 8 + tg * 2;
        float2 asv = *(const float2*)&a_src[colc];
        float2 adv = *(const float2*)&a_dst[colc];
        ps0 += acc[j][0] * asv.x + acc[j][1] * asv.y;
        pd0 += acc[j][0] * adv.x + acc[j][1] * adv.y;
        ps1 += acc[j][2] * asv.x + acc[j][3] * asv.y;
        pd1 += acc[j][2] * adv.x + acc[j][3] * adv.y;
        if (r0g < NN)
            *(__half2*)&H[r0g * DD + colc] = __floats2half2_rn(acc[j][0], acc[j][1]);
        if (r1g < NN)
            *(__half2*)&H[r1g * DD + colc] = __floats2half2_rn(acc[j][2], acc[j][3]);
    }
#pragma unroll
    for (int off = 1; off < 4; off <<= 1) {
        ps0 += __shfl_xor_sync(0xffffffffu, ps0, off);
        pd0 += __shfl_xor_sync(0xffffffffu, pd0, off);
        ps1 += __shfl_xor_sync(0xffffffffu, ps1, off);
        pd1 += __shfl_xor_sync(0xffffffffu, pd1, off);
    }
    float lms = -1e30f, lmd = -1e30f;
    if (tg == 0) {
        if (r0g < NN) {
            ssrc[r0g] = ps0; sdst[r0g] = pd0;
            lms = ps0; lmd = pd0;
        }
        if (r1g < NN) {
            ssrc[r1g] = ps1; sdst[r1g] = pd1;
            lms = fmaxf(lms, ps1); lmd = fmaxf(lmd, pd1);
        }
    }
#pragma unroll
    for (int off = 16; off; off >>= 1) {
        lms = fmaxf(lms, __shfl_xor_sync(0xffffffffu, lms, off));
        lmd = fmaxf(lmd, __shfl_xor_sync(0xffffffffu, lmd, off));
    }
    if (l == 0) { s_red[wid][0] = lms; s_red[wid][1] = lmd; }
    __syncthreads();
    if (tid == 0) {
        float ms = s_red[0][0], md = s_red[0][1];
#pragma unroll
        for (int i = 1; i < 8; ++i) {
            ms = fmaxf(ms, s_red[i][0]);
            md = fmaxf(md, s_red[i][1]);
        }
        atomicMax(&g_gmax[2 * slot], encf(ms));
        atomicMax(&g_gmax[2 * slot + 1], encf(md));
    }
}

// ---------------- shared edge-softmax accumulate (warp-per-dst) ----------------
__device__ __forceinline__ void agg_row(const int* __restrict__ col,
                                        const float* __restrict__ ss,
                                        const uint2* __restrict__ h2,
                                        int beg, int end, int l,
                                        float sd, float c,
                                        float4& acc, float& den) {
    int e = beg;
    for (; e + 8 <= end; e += 8) {
        int s[8];
        float wt[8];
#pragma unroll
        for (int q = 0; q < 8; ++q) s[q] = col[e + q];
#pragma unroll
        for (int q = 0; q < 8; ++q) wt[q] = __expf(lrelu(ss[s[q]] + sd) - c);
#pragma unroll
        for (int q = 0; q < 8; ++q) {
            uint2 r = h2[s[q] * 32 + l];
            float2 a = __half22float2(*(__half2*)&r.x);
            float2 b = __half22float2(*(__half2*)&r.y);
            den += wt[q];
            acc.x += wt[q] * a.x; acc.y += wt[q] * a.y;
            acc.z += wt[q] * b.x; acc.w += wt[q] * b.y;
        }
    }
    if (e + 4 <= end) {
        int s[4];
        float wt[4];
#pragma unroll
        for (int q = 0; q < 4; ++q) s[q] = col[e + q];
#pragma unroll
        for (int q = 0; q < 4; ++q) wt[q] = __expf(lrelu(ss[s[q]] + sd) - c);
#pragma unroll
        for (int q = 0; q < 4; ++q) {
            uint2 r = h2[s[q] * 32 + l];
            float2 a = __half22float2(*(__half2*)&r.x);
            float2 b = __half22float2(*(__half2*)&r.y);
            den += wt[q];
            acc.x += wt[q] * a.x; acc.y += wt[q] * a.y;
            acc.z += wt[q] * b.x; acc.w += wt[q] * b.y;
        }
        e += 4;
    }
    for (; e < end; ++e) {
        int s = col[e];
        float wgt = __expf(lrelu(ss[s] + sd) - c);
        uint2 r = h2[s * 32 + l];
        float2 a = __half22float2(*(__half2*)&r.x);
        float2 b = __half22float2(*(__half2*)&r.y);
        den += wgt;
        acc.x += wgt * a.x; acc.y += wgt * a.y;
        acc.z += wgt * b.x; acc.w += wgt * b.y;
    }
}

// ---------------- layer-1 aggregate (both branches via grid.y) ----------------
__global__ __launch_bounds__(256) void k_aggregate1(const float* __restrict__ bias0,
                                                    const float* __restrict__ bias1) {
    int b = blockIdx.y;
    const int* __restrict__ rowptr = g_rowptr + b * (NN + 1);
    const int* __restrict__ col    = g_col + b * TOTE;
    const float* __restrict__ bias = b ? bias1 : bias0;
    int w = (blockIdx.x * blockDim.x + threadIdx.x) >> 5;
    int l = threadIdx.x & 31;
    if (w >= NN) return;
    float c = lrelu(decf(g_gmax[2 * b]) + decf(g_gmax[2 * b + 1]));
    float sd = g_sdst[b * NN + w];
    int beg = __ldg(&rowptr[w]);
    int end = __ldg(&rowptr[w + 1]);
    float4 acc = make_float4(0.f, 0.f, 0.f, 0.f);
    float den = 0.f;
    agg_row(col, g_ssrc + b * NN, (const uint2*)g_h16[b], beg, end, l, sd, c, acc, den);
    float inv = 1.f / (den + 1e-16f);
    float2 bv0 = ((const float2*)bias)[2 * l];
    float2 bv1 = ((const float2*)bias)[2 * l + 1];
    float4 o;
    o.x = fmaxf(acc.x * inv + bv0.x, 0.f);
    o.y = fmaxf(acc.y * inv + bv0.y, 0.f);
    o.z = fmaxf(acc.z * inv + bv1.x, 0.f);
    o.w = fmaxf(acc.w * inv + bv1.y, 0.f);
    __half2 h0 = __floats2half2_rn(o.x, o.y);
    __half2 h1 = __floats2half2_rn(o.z, o.w);
    uint2 p;
    p.x = *(unsigned*)&h0;
    p.y = *(unsigned*)&h1;
    ((uint2*)g_a16[b])[w * 32 + l] = p;
}

// ---------------- layer-2 aggregate + fused pred head ----------------
__global__ __launch_bounds__(256) void k_agg2pred(const float* __restrict__ bias0,
                                                  const float* __restrict__ bias1,
                                                  const float* __restrict__ degree,
                                                  const float* __restrict__ Wp,
                                                  const float* __restrict__ bp,
                                                  float* __restrict__ out) {
    int w = (blockIdx.x * blockDim.x + threadIdx.x) >> 5;
    int l = threadIdx.x & 31;
    if (w >= NN) return;
    float4 xb[2];
#pragma unroll
    for (int b = 0; b < 2; ++b) {
        const int* __restrict__ rowptr = g_rowptr + b * (NN + 1);
        const int* __restrict__ col    = g_col + b * TOTE;
        const float* __restrict__ bias = b ? bias1 : bias0;
        float c = lrelu(decf(g_gmax[4 + 2 * b]) + decf(g_gmax[4 + 2 * b + 1]));
        float sd = g_sdst[b * NN + w];
        int beg = __ldg(&rowptr[w]);
        int end = __ldg(&rowptr[w + 1]);
        float4 acc = make_float4(0.f, 0.f, 0.f, 0.f);
        float den = 0.f;
        agg_row(col, g_ssrc + b * NN, (const uint2*)g_h16[b], beg, end, l, sd, c, acc, den);
        float inv = 1.f / (den + 1e-16f);
        float2 bv0 = ((const float2*)bias)[2 * l];
        float2 bv1 = ((const float2*)bias)[2 * l + 1];
        xb[b].x = acc.x * inv + bv0.x;
        xb[b].y = acc.y * inv + bv0.y;
        xb[b].z = acc.z * inv + bv1.x;
        xb[b].w = acc.w * inv + bv1.y;
    }
    float4 xo = xb[0], xs = xb[1];
    float dg = degree[w * 32 + l];
    int k0 = l * 4;
    float z0 = xo.x * Wp[(k0 + 0) * 2] + xo.y * Wp[(k0 + 1) * 2]
             + xo.z * Wp[(k0 + 2) * 2] + xo.w * Wp[(k0 + 3) * 2]
             + xs.x * Wp[(128 + k0 + 0) * 2] + xs.y * Wp[(128 + k0 + 1) * 2]
             + xs.z * Wp[(128 + k0 + 2) * 2] + xs.w * Wp[(128 + k0 + 3) * 2]
             + dg * Wp[(256 + l) * 2];
    float z1 = xo.x * Wp[(k0 + 0) * 2 + 1] + xo.y * Wp[(k0 + 1) * 2 + 1]
             + xo.z * Wp[(k0 + 2) * 2 + 1] + xo.w * Wp[(k0 + 3) * 2 + 1]
             + xs.x * Wp[(128 + k0 + 0) * 2 + 1] + xs.y * Wp[(128 + k0 + 1) * 2 + 1]
             + xs.z * Wp[(128 + k0 + 2) * 2 + 1] + xs.w * Wp[(128 + k0 + 3) * 2 + 1]
             + dg * Wp[(256 + l) * 2 + 1];
#pragma unroll
    for (int off = 16; off; off >>= 1) {
        z0 += __shfl_xor_sync(0xffffffffu, z0, off);
        z1 += __shfl_xor_sync(0xffffffffu, z1, off);
    }
    z0 += bp[0];
    z1 += bp[1];
    float mz = fmaxf(z0, z1);
    float e0 = __expf(z0 - mz), e1 = __expf(z1 - mz);
    float inv = 1.f / (e0 + e1);
    float a0 = e0 * inv, a1 = e1 * inv;
    float4 o;
    o.x = a0 * xo.x + a1 * xs.x;
    o.y = a0 * xo.y + a1 * xs.y;
    o.z = a0 * xo.z + a1 * xs.z;
    o.w = a0 * xo.w + a1 * xs.w;
    ((float4*)out)[w * 32 + l] = o;
}

extern "C" void kernel_launch(void* const* d_in, const int* in_sizes, int n_in,
                              void* d_out, int out_size) {
    const float* x_o    = (const float*)d_in[0];
    const float* degree = (const float*)d_in[1];
    const int *ei_o, *ei_s;
    int base;
    if (in_sizes[2] == 2 * EDGES) {
        ei_o = (const int*)d_in[2];
        ei_s = (const int*)d_in[3];
        base = 4;
    } else {
        base = 2;
        ei_o = (const int*)d_in[20];
        ei_s = (const int*)d_in[21];
    }
    const float* W_o1 = (const float*)d_in[base + 0];
    const float* a_src_o1 = (const float*)d_in[base + 1];
    const float* a_dst_o1 = (const float*)d_in[base + 2];
    const float* b_o1 = (const float*)d_in[base + 3];
    const float* W_o2 = (const float*)d_in[base + 4];
    const float* a_src_o2 = (const float*)d_in[base + 5];
    const float* a_dst_o2 = (const float*)d_in[base + 6];
    const float* b_o2 = (const float*)d_in[base + 7];
    const float* W_s1 = (const float*)d_in[base + 8];
    const float* a_src_s1 = (const float*)d_in[base + 9];
    const float* a_dst_s1 = (const float*)d_in[base + 10];
    const float* b_s1 = (const float*)d_in[base + 11];
    const float* W_s2 = (const float*)d_in[base + 12];
    const float* a_src_s2 = (const float*)d_in[base + 13];
    const float* a_dst_s2 = (const float*)d_in[base + 14];
    const float* b_s2 = (const float*)d_in[base + 15];
    const float* W_pred = (const float*)d_in[base + 16];
    const float* b_pred = (const float*)d_in[base + 17];
    float* out = (float*)d_out;

    cudaFuncSetAttribute(k_gemm, cudaFuncAttributeMaxDynamicSharedMemorySize, GEMM_SMEM);

    k_prep_count<<<WCONV_BLKS + COUNT_BLKS, 256>>>(W_o1, W_s1, W_o2, W_s2, ei_o, ei_s);
    k_csr<<<98, 1024>>>();
    k_fill_conv<<<COUNT_BLKS + XCONV_BLKS, 256>>>(x_o, ei_o, ei_s);
    k_gemm<<<dim3(GEMM_TILES, 2), 256, GEMM_SMEM>>>(0, a_src_o1, a_src_s1, a_dst_o1, a_dst_s1);
    k_aggregate1<<<dim3(NN / 8, 2), 256>>>(b_o1, b_s1);
    k_gemm<<<dim3(GEMM_TILES, 2), 256, GEMM_SMEM>>>(1, a_src_o2, a_src_s2, a_dst_o2, a_dst_s2);
    k_agg2pred<<<NN / 8, 256>>>(b_o2, b_s2, degree, W_pred, b_pred, out);
}

// round 16
// speedup vs baseline: 1.0407x; 1.0219x over previous
#include <cuda_runtime.h>
#include <cuda_fp16.h>

#define NN 50000
#define EDGES 1000000
#define DD 128
#define TOTE (EDGES + NN)

// ---------------- scratch ----------------
__device__ __half g_h16[2][NN * DD];   // per-branch transformed features
__device__ __half g_xin16[NN * DD];    // fp16 x_o
__device__ __half g_a16[2][NN * DD];   // per-branch fp16 x1
__device__ __half g_w16[4][DD * DD];   // fp16 weights: slot = layer*2 + branch
__device__ float g_ssrc[2 * NN];
__device__ float g_sdst[2 * NN];
__device__ unsigned g_gmax[8];
__device__ int   g_deg[2 * NN];        // zero at start; reset by k_csr each run
__device__ int   g_epos[2 * EDGES];    // per-edge slot position (from count atomics)
__device__ int   g_bsum[128];
__device__ int   g_sflag[128];         // look-back flags (zeroed in prep)
__device__ int   g_rowptr[2 * (NN + 1)];
__device__ int   g_col[2 * TOTE];

__device__ __forceinline__ unsigned encf(float f) {
    unsigned u = __float_as_uint(f);
    return (u & 0x80000000u) ? ~u : (u | 0x80000000u);
}
__device__ __forceinline__ float decf(unsigned u) {
    return __uint_as_float((u & 0x80000000u) ? (u & 0x7fffffffu) : ~u);
}
__device__ __forceinline__ float lrelu(float z) { return z > 0.f ? z : 0.2f * z; }

__device__ __forceinline__ void cp_async16(void* smem_dst, const void* gmem_src) {
    unsigned dst = (unsigned)__cvta_generic_to_shared(smem_dst);
    asm volatile("cp.async.cg.shared.global [%0], [%1], 16;" :: "r"(dst), "l"(gmem_src));
}

// ---------------- merged: W fp16 conversion + inits + degree count (stores slot pos) ----------------
#define WCONV_BLKS 64    // 4 matrices * 4096 float4 / 256
#define COUNT_BLKS ((2 * EDGES / 4 + 255) / 256)   // 1954
__global__ void k_prep_count(const float* __restrict__ W0, const float* __restrict__ W1,
                             const float* __restrict__ W2, const float* __restrict__ W3,
                             const int* __restrict__ ei_o,
                             const int* __restrict__ ei_s) {
    if (blockIdx.x < WCONV_BLKS) {
        int j = blockIdx.x * 256 + threadIdx.x;   // 0..16383
        int m = j >> 12;
        int q = j & 4095;
        const float* Wm = (m == 0) ? W0 : (m == 1) ? W1 : (m == 2) ? W2 : W3;
        float4 v = ((const float4*)Wm)[q];
        uint2 p;
        __half2 h0 = __floats2half2_rn(v.x, v.y);
        __half2 h1 = __floats2half2_rn(v.z, v.w);
        p.x = *(unsigned*)&h0;
        p.y = *(unsigned*)&h1;
        ((uint2*)g_w16[m])[q] = p;
        if (blockIdx.x == 0) {
            if (threadIdx.x < 8) g_gmax[threadIdx.x] = encf(-1e30f);
            if (threadIdx.x < 128) g_sflag[threadIdx.x] = 0;
        }
    } else {
        int t = (blockIdx.x - WCONV_BLKS) * 256 + threadIdx.x;
        int e0 = t * 4;
        if (e0 >= 2 * EDGES) return;
        int g = (e0 >= EDGES);
        int le = e0 - g * EDGES;
        const int* ei = g ? ei_s : ei_o;
        int* deg = g_deg + g * NN;
        if (le + 4 <= EDGES) {
            int4 d4 = *(const int4*)&ei[EDGES + le];
            int4 ps;
            ps.x = atomicAdd(&deg[d4.x], 1);
            ps.y = atomicAdd(&deg[d4.y], 1);
            ps.z = atomicAdd(&deg[d4.z], 1);
            ps.w = atomicAdd(&deg[d4.w], 1);
            *(int4*)&g_epos[e0] = ps;
        } else {
            for (int q = 0; q < 4 && le + q < EDGES; ++q)
                g_epos[e0 + q] = atomicAdd(&deg[ei[EDGES + le + q]], 1);
        }
    }
}

// ---------------- CSR: scan + self-loop fill (decoupled look-back) ----------------
__global__ void k_csr() {
    __shared__ int wsum[32];
    __shared__ int s_boff;
    int tid = threadIdx.x;
    int lane = tid & 31;
    int wid = tid >> 5;
    int g = (blockIdx.x >= 49);
    int lb = blockIdx.x - g * 49;
    int idx = lb * 1024 + tid;
    int v = (idx < NN) ? (g_deg[g * NN + idx] + 1) : 0;   // +1 = self loop
    int sc = v;
#pragma unroll
    for (int off = 1; off < 32; off <<= 1) {
        int t = __shfl_up_sync(0xffffffffu, sc, off);
        if (lane >= off) sc += t;
    }
    if (lane == 31) wsum[wid] = sc;
    __syncthreads();
    if (wid == 0) {
        int ws = wsum[lane];
#pragma unroll
        for (int off = 1; off < 32; off <<= 1) {
            int t = __shfl_up_sync(0xffffffffu, ws, off);
            if (lane >= off) ws += t;
        }
        wsum[lane] = ws;
    }
    __syncthreads();
    int incl = sc + (wid ? wsum[wid - 1] : 0);
    int total = wsum[31];
    if (tid == 0) {
        g_bsum[g * 64 + lb] = total;
        __threadfence();
        *((volatile int*)&g_sflag[g * 64 + lb]) = 1;
    }
    if (wid == 0) {
        int acc = 0;
#pragma unroll
        for (int half = 0; half < 2; ++half) {
            int j = lane + half * 32;
            if (j < lb) {
                while (*((volatile int*)&g_sflag[g * 64 + j]) == 0) { }
                acc += *((volatile int*)&g_bsum[g * 64 + j]);
            }
        }
#pragma unroll
        for (int off = 16; off; off >>= 1)
            acc += __shfl_xor_sync(0xffffffffu, acc, off);
        if (lane == 0) s_boff = acc;
    }
    __syncthreads();
    int boff = s_boff;
    if (idx < NN) {
        int p = incl - v + boff;
        g_rowptr[g * (NN + 1) + idx] = p;
        g_col[g * TOTE + p] = idx;     // self loop at slot 0 of the row
        g_deg[g * NN + idx] = 0;       // reset for next replay
    }
    if (idx == 0) g_rowptr[g * (NN + 1) + NN] = TOTE;
}

// ---------------- merged: atomic-free edge fill FIRST, then x->fp16 conversion ----------------
#define XCONV_BLKS 6250   // NN*DD/4 float4 / 256
__global__ __launch_bounds__(256) void k_fill_conv(const float* __restrict__ x,
                                                   const int* __restrict__ ei_o,
                                                   const int* __restrict__ ei_s) {
    if (blockIdx.x < COUNT_BLKS) {
        int t = blockIdx.x * 256 + threadIdx.x;
        int e0 = t * 4;
        if (e0 >= 2 * EDGES) return;
        int g = (e0 >= EDGES);
        int le = e0 - g * EDGES;
        const int* ei = g ? ei_s : ei_o;
        const int* __restrict__ rowptr = g_rowptr + g * (NN + 1);
        int* col = g_col + g * TOTE;
        if (le + 4 <= EDGES) {
            int4 s4 = *(const int4*)&ei[le];
            int4 d4 = *(const int4*)&ei[EDGES + le];
            int4 ps = *(const int4*)&g_epos[e0];
            col[__ldg(&rowptr[d4.x]) + 1 + ps.x] = s4.x;
            col[__ldg(&rowptr[d4.y]) + 1 + ps.y] = s4.y;
            col[__ldg(&rowptr[d4.z]) + 1 + ps.z] = s4.z;
            col[__ldg(&rowptr[d4.w]) + 1 + ps.w] = s4.w;
        } else {
            for (int q = 0; q < 4 && le + q < EDGES; ++q) {
                int s = ei[le + q];
                int d = ei[EDGES + le + q];
                col[__ldg(&rowptr[d]) + 1 + g_epos[e0 + q]] = s;
            }
        }
    } else {
        int i = (blockIdx.x - COUNT_BLKS) * 256 + threadIdx.x;
        float4 v = ((const float4*)x)[i];
        uint2 p;
        __half2 h0 = __floats2half2_rn(v.x, v.y);
        __half2 h1 = __floats2half2_rn(v.z, v.w);
        p.x = *(unsigned*)&h0;
        p.y = *(unsigned*)&h1;
        ((uint2*)g_xin16)[i] = p;
    }
}

// ---------------- HMMA GEMM: M=128, 2-stage K pipeline (64 per stage) ----------------
#define APITCH 72
#define BPITCH 136
#define A_STAGE (128 * APITCH)
#define B_STAGE (64 * BPITCH)

__device__ __forceinline__ void ldsm_x4(unsigned& r0, unsigned& r1, unsigned& r2, unsigned& r3,
                                        unsigned addr) {
    asm volatile("ldmatrix.sync.aligned.m8n8.x4.shared.b16 {%0,%1,%2,%3}, [%4];"
                 : "=r"(r0), "=r"(r1), "=r"(r2), "=r"(r3) : "r"(addr));
}
__device__ __forceinline__ void ldsm_x4_t(unsigned& r0, unsigned& r1, unsigned& r2, unsigned& r3,
                                          unsigned addr) {
    asm volatile("ldmatrix.sync.aligned.m8n8.x4.trans.shared.b16 {%0,%1,%2,%3}, [%4];"
                 : "=r"(r0), "=r"(r1), "=r"(r2), "=r"(r3) : "r"(addr));
}
__device__ __forceinline__ void hmma(float* d, unsigned a0, unsigned a1, unsigned a2, unsigned a3,
                                     unsigned b0, unsigned b1) {
    asm volatile("mma.sync.aligned.m16n8k16.row.col.f32.f16.f16.f32 "
                 "{%0,%1,%2,%3}, {%4,%5,%6,%7}, {%8,%9}, {%0,%1,%2,%3};"
                 : "+f"(d[0]), "+f"(d[1]), "+f"(d[2]), "+f"(d[3])
                 : "r"(a0), "r"(a1), "r"(a2), "r"(a3), "r"(b0), "r"(b1));
}

#define GEMM_TILES 392          // ceil(NN/128)
#define GEMM_SMEM ((2 * A_STAGE + 2 * B_STAGE) * 2)   // 71680 bytes

__global__ __launch_bounds__(256, 2) void k_gemm(
    int layer,
    const float* __restrict__ as0, const float* __restrict__ as1,
    const float* __restrict__ ad0, const float* __restrict__ ad1)
{
    int b = blockIdx.y;
    const __half* __restrict__ A = (layer == 0) ? g_xin16 : g_a16[b];
    int slot = layer * 2 + b;
    const __half* __restrict__ Wh = g_w16[slot];
    const float* __restrict__ a_src = b ? as1 : as0;
    const float* __restrict__ a_dst = b ? ad1 : ad0;
    __half* __restrict__ H = g_h16[b];
    float* __restrict__ ssrc = g_ssrc + b * NN;
    float* __restrict__ sdst = g_sdst + b * NN;

    extern __shared__ __half sh[];
    __half* Ast[2] = { sh, sh + A_STAGE };
    __half* Bst[2] = { sh + 2 * A_STAGE, sh + 2 * A_STAGE + B_STAGE };
    __shared__ float s_red[8][2];
    int tid = threadIdx.x;
    int l = tid & 31;
    int wid = tid >> 5;
    int row0 = blockIdx.x * 128;

#pragma unroll
    for (int s = 0; s < 2; ++s) {
#pragma unroll
        for (int t = 0; t < 4; ++t) {
            int i = t * 256 + tid;
            int r = i >> 3;
            int c = i & 7;
            if (row0 + r < NN)
                cp_async16(&Ast[s][r * APITCH + c * 8], &A[(row0 + r) * DD + s * 64 + c * 8]);
            else
                *(uint4*)&Ast[s][r * APITCH + c * 8] = make_uint4(0u, 0u, 0u, 0u);
        }
#pragma unroll
        for (int t = 0; t < 4; ++t) {
            int i = t * 256 + tid;
            int r = i >> 4;
            int c = i & 15;
            cp_async16(&Bst[s][r * BPITCH + c * 8], &Wh[(s * 64 + r) * DD + c * 8]);
        }
        asm volatile("cp.async.commit_group;");
    }

    float acc[16][4];
#pragma unroll
    for (int j = 0; j < 16; ++j)
#pragma unroll
        for (int q = 0; q < 4; ++q) acc[j][q] = 0.f;

    int arow = wid * 16 + (l & 15);
    int acolo = (l >> 4) * 8;
    int brow = l & 15;
    int bcolo = (l >> 4) * 8;

#pragma unroll
    for (int s = 0; s < 2; ++s) {
        if (s == 0)
            asm volatile("cp.async.wait_group 1;");
        else
            asm volatile("cp.async.wait_group 0;");
        __syncthreads();
        unsigned a_base = (unsigned)__cvta_generic_to_shared(&Ast[s][arow * APITCH + acolo]);
        unsigned b_base = (unsigned)__cvta_generic_to_shared(&Bst[s][brow * BPITCH + bcolo]);
#pragma unroll
        for (int ks = 0; ks < 4; ++ks) {
            unsigned a0, a1, a2, a3;
            ldsm_x4(a0, a1, a2, a3, a_base + (unsigned)(ks * 16 * 2));
#pragma unroll
            for (int np = 0; np < 8; ++np) {
                unsigned b0, b1, b2, b3;
                ldsm_x4_t(b0, b1, b2, b3,
                          b_base + (unsigned)((ks * 16 * BPITCH + np * 16) * 2));
                hmma(acc[2 * np], a0, a1, a2, a3, b0, b1);
                hmma(acc[2 * np + 1], a0, a1, a2, a3, b2, b3);
            }
        }
    }

    // epilogue: write h fp16, fused s_src/s_dst
    int g = l >> 2, tg = l & 3;
    int r0g = row0 + wid * 16 + g;
    int r1g = r0g + 8;
    float ps0 = 0.f, pd0 = 0.f, ps1 = 0.f, pd1 = 0.f;
#pragma unroll
    for (int j = 0; j < 16; ++j) {
        int colc = j * 8 + tg * 2;
        float2 asv = *(const float2*)&a_src[colc];
        float2 adv = *(const float2*)&a_dst[colc];
        ps0 += acc[j][0] * asv.x + acc[j][1] * asv.y;
        pd0 += acc[j][0] * adv.x + acc[j][1] * adv.y;
        ps1 += acc[j][2] * asv.x + acc[j][3] * asv.y;
        pd1 += acc[j][2] * adv.x + acc[j][3] * adv.y;
        if (r0g < NN)
            *(__half2*)&H[r0g * DD + colc] = __floats2half2_rn(acc[j][0], acc[j][1]);
        if (r1g < NN)
            *(__half2*)&H[r1g * DD + colc] = __floats2half2_rn(acc[j][2], acc[j][3]);
    }
#pragma unroll
    for (int off = 1; off < 4; off <<= 1) {
        ps0 += __shfl_xor_sync(0xffffffffu, ps0, off);
        pd0 += __shfl_xor_sync(0xffffffffu, pd0, off);
        ps1 += __shfl_xor_sync(0xffffffffu, ps1, off);
        pd1 += __shfl_xor_sync(0xffffffffu, pd1, off);
    }
    float lms = -1e30f, lmd = -1e30f;
    if (tg == 0) {
        if (r0g < NN) {
            ssrc[r0g] = ps0; sdst[r0g] = pd0;
            lms = ps0; lmd = pd0;
        }
        if (r1g < NN) {
            ssrc[r1g] = ps1; sdst[r1g] = pd1;
            lms = fmaxf(lms, ps1); lmd = fmaxf(lmd, pd1);
        }
    }
#pragma unroll
    for (int off = 16; off; off >>= 1) {
        lms = fmaxf(lms, __shfl_xor_sync(0xffffffffu, lms, off));
        lmd = fmaxf(lmd, __shfl_xor_sync(0xffffffffu, lmd, off));
    }
    if (l == 0) { s_red[wid][0] = lms; s_red[wid][1] = lmd; }
    __syncthreads();
    if (tid == 0) {
        float ms = s_red[0][0], md = s_red[0][1];
#pragma unroll
        for (int i = 1; i < 8; ++i) {
            ms = fmaxf(ms, s_red[i][0]);
            md = fmaxf(md, s_red[i][1]);
        }
        atomicMax(&g_gmax[2 * slot], encf(ms));
        atomicMax(&g_gmax[2 * slot + 1], encf(md));
    }
}

// ---------------- shared edge-softmax accumulate (warp-per-dst) ----------------
__device__ __forceinline__ void agg_row(const int* __restrict__ col,
                                        const float* __restrict__ ss,
                                        const uint2* __restrict__ h2,
                                        int beg, int end, int l,
                                        float sd, float c,
                                        float4& acc, float& den) {
    int e = beg;
    for (; e + 8 <= end; e += 8) {
        int s[8];
        float wt[8];
#pragma unroll
        for (int q = 0; q < 8; ++q) s[q] = col[e + q];
#pragma unroll
        for (int q = 0; q < 8; ++q) wt[q] = __expf(lrelu(ss[s[q]] + sd) - c);
#pragma unroll
        for (int q = 0; q < 8; ++q) {
            uint2 r = h2[s[q] * 32 + l];
            float2 a = __half22float2(*(__half2*)&r.x);
            float2 b = __half22float2(*(__half2*)&r.y);
            den += wt[q];
            acc.x += wt[q] * a.x; acc.y += wt[q] * a.y;
            acc.z += wt[q] * b.x; acc.w += wt[q] * b.y;
        }
    }
    if (e + 4 <= end) {
        int s[4];
        float wt[4];
#pragma unroll
        for (int q = 0; q < 4; ++q) s[q] = col[e + q];
#pragma unroll
        for (int q = 0; q < 4; ++q) wt[q] = __expf(lrelu(ss[s[q]] + sd) - c);
#pragma unroll
        for (int q = 0; q < 4; ++q) {
            uint2 r = h2[s[q] * 32 + l];
            float2 a = __half22float2(*(__half2*)&r.x);
            float2 b = __half22float2(*(__half2*)&r.y);
            den += wt[q];
            acc.x += wt[q] * a.x; acc.y += wt[q] * a.y;
            acc.z += wt[q] * b.x; acc.w += wt[q] * b.y;
        }
        e += 4;
    }
    for (; e < end; ++e) {
        int s = col[e];
        float wgt = __expf(lrelu(ss[s] + sd) - c);
        uint2 r = h2[s * 32 + l];
        float2 a = __half22float2(*(__half2*)&r.x);
        float2 b = __half22float2(*(__half2*)&r.y);
        den += wgt;
        acc.x += wgt * a.x; acc.y += wgt * a.y;
        acc.z += wgt * b.x; acc.w += wgt * b.y;
    }
}

// ---------------- layer-1 aggregate (both branches via grid.y) ----------------
__global__ __launch_bounds__(256) void k_aggregate1(const float* __restrict__ bias0,
                                                    const float* __restrict__ bias1) {
    int b = blockIdx.y;
    const int* __restrict__ rowptr = g_rowptr + b * (NN + 1);
    const int* __restrict__ col    = g_col + b * TOTE;
    const float* __restrict__ bias = b ? bias1 : bias0;
    int w = (blockIdx.x * blockDim.x + threadIdx.x) >> 5;
    int l = threadIdx.x & 31;
    if (w >= NN) return;
    float c = lrelu(decf(g_gmax[2 * b]) + decf(g_gmax[2 * b + 1]));
    float sd = g_sdst[b * NN + w];
    int beg = __ldg(&rowptr[w]);
    int end = __ldg(&rowptr[w + 1]);
    float4 acc = make_float4(0.f, 0.f, 0.f, 0.f);
    float den = 0.f;
    agg_row(col, g_ssrc + b * NN, (const uint2*)g_h16[b], beg, end, l, sd, c, acc, den);
    float inv = 1.f / (den + 1e-16f);
    float2 bv0 = ((const float2*)bias)[2 * l];
    float2 bv1 = ((const float2*)bias)[2 * l + 1];
    float4 o;
    o.x = fmaxf(acc.x * inv + bv0.x, 0.f);
    o.y = fmaxf(acc.y * inv + bv0.y, 0.f);
    o.z = fmaxf(acc.z * inv + bv1.x, 0.f);
    o.w = fmaxf(acc.w * inv + bv1.y, 0.f);
    __half2 h0 = __floats2half2_rn(o.x, o.y);
    __half2 h1 = __floats2half2_rn(o.z, o.w);
    uint2 p;
    p.x = *(unsigned*)&h0;
    p.y = *(unsigned*)&h1;
    ((uint2*)g_a16[b])[w * 32 + l] = p;
}

// ---------------- layer-2 aggregate + fused pred head ----------------
__global__ __launch_bounds__(256) void k_agg2pred(const float* __restrict__ bias0,
                                                  const float* __restrict__ bias1,
                                                  const float* __restrict__ degree,
                                                  const float* __restrict__ Wp,
                                                  const float* __restrict__ bp,
                                                  float* __restrict__ out) {
    int w = (blockIdx.x * blockDim.x + threadIdx.x) >> 5;
    int l = threadIdx.x & 31;
    if (w >= NN) return;
    float4 xb[2];
#pragma unroll
    for (int b = 0; b < 2; ++b) {
        const int* __restrict__ rowptr = g_rowptr + b * (NN + 1);
        const int* __restrict__ col    = g_col + b * TOTE;
        const float* __restrict__ bias = b ? bias1 : bias0;
        float c = lrelu(decf(g_gmax[4 + 2 * b]) + decf(g_gmax[4 + 2 * b + 1]));
        float sd = g_sdst[b * NN + w];
        int beg = __ldg(&rowptr[w]);
        int end = __ldg(&rowptr[w + 1]);
        float4 acc = make_float4(0.f, 0.f, 0.f, 0.f);
        float den = 0.f;
        agg_row(col, g_ssrc + b * NN, (const uint2*)g_h16[b], beg, end, l, sd, c, acc, den);
        float inv = 1.f / (den + 1e-16f);
        float2 bv0 = ((const float2*)bias)[2 * l];
        float2 bv1 = ((const float2*)bias)[2 * l + 1];
        xb[b].x = acc.x * inv + bv0.x;
        xb[b].y = acc.y * inv + bv0.y;
        xb[b].z = acc.z * inv + bv1.x;
        xb[b].w = acc.w * inv + bv1.y;
    }
    float4 xo = xb[0], xs = xb[1];
    float dg = degree[w * 32 + l];
    int k0 = l * 4;
    float z0 = xo.x * Wp[(k0 + 0) * 2] + xo.y * Wp[(k0 + 1) * 2]
             + xo.z * Wp[(k0 + 2) * 2] + xo.w * Wp[(k0 + 3) * 2]
             + xs.x * Wp[(128 + k0 + 0) * 2] + xs.y * Wp[(128 + k0 + 1) * 2]
             + xs.z * Wp[(128 + k0 + 2) * 2] + xs.w * Wp[(128 + k0 + 3) * 2]
             + dg * Wp[(256 + l) * 2];
    float z1 = xo.x * Wp[(k0 + 0) * 2 + 1] + xo.y * Wp[(k0 + 1) * 2 + 1]
             + xo.z * Wp[(k0 + 2) * 2 + 1] + xo.w * Wp[(k0 + 3) * 2 + 1]
             + xs.x * Wp[(128 + k0 + 0) * 2 + 1] + xs.y * Wp[(128 + k0 + 1) * 2 + 1]
             + xs.z * Wp[(128 + k0 + 2) * 2 + 1] + xs.w * Wp[(128 + k0 + 3) * 2 + 1]
             + dg * Wp[(256 + l) * 2 + 1];
#pragma unroll
    for (int off = 16; off; off >>= 1) {
        z0 += __shfl_xor_sync(0xffffffffu, z0, off);
        z1 += __shfl_xor_sync(0xffffffffu, z1, off);
    }
    z0 += bp[0];
    z1 += bp[1];
    float mz = fmaxf(z0, z1);
    float e0 = __expf(z0 - mz), e1 = __expf(z1 - mz);
    float inv = 1.f / (e0 + e1);
    float a0 = e0 * inv, a1 = e1 * inv;
    float4 o;
    o.x = a0 * xo.x + a1 * xs.x;
    o.y = a0 * xo.y + a1 * xs.y;
    o.z = a0 * xo.z + a1 * xs.z;
    o.w = a0 * xo.w + a1 * xs.w;
    ((float4*)out)[w * 32 + l] = o;
}

extern "C" void kernel_launch(void* const* d_in, const int* in_sizes, int n_in,
                              void* d_out, int out_size) {
    const float* x_o    = (const float*)d_in[0];
    const float* degree = (const float*)d_in[1];
    const int *ei_o, *ei_s;
    int base;
    if (in_sizes[2] == 2 * EDGES) {
        ei_o = (const int*)d_in[2];
        ei_s = (const int*)d_in[3];
        base = 4;
    } else {
        base = 2;
        ei_o = (const int*)d_in[20];
        ei_s = (const int*)d_in[21];
    }
    const float* W_o1 = (const float*)d_in[base + 0];
    const float* a_src_o1 = (const float*)d_in[base + 1];
    const float* a_dst_o1 = (const float*)d_in[base + 2];
    const float* b_o1 = (const float*)d_in[base + 3];
    const float* W_o2 = (const float*)d_in[base + 4];
    const float* a_src_o2 = (const float*)d_in[base + 5];
    const float* a_dst_o2 = (const float*)d_in[base + 6];
    const float* b_o2 = (const float*)d_in[base + 7];
    const float* W_s1 = (const float*)d_in[base + 8];
    const float* a_src_s1 = (const float*)d_in[base + 9];
    const float* a_dst_s1 = (const float*)d_in[base + 10];
    const float* b_s1 = (const float*)d_in[base + 11];
    const float* W_s2 = (const float*)d_in[base + 12];
    const float* a_src_s2 = (const float*)d_in[base + 13];
    const float* a_dst_s2 = (const float*)d_in[base + 14];
    const float* b_s2 = (const float*)d_in[base + 15];
    const float* W_pred = (const float*)d_in[base + 16];
    const float* b_pred = (const float*)d_in[base + 17];
    float* out = (float*)d_out;

    cudaFuncSetAttribute(k_gemm, cudaFuncAttributeMaxDynamicSharedMemorySize, GEMM_SMEM);

    k_prep_count<<<WCONV_BLKS + COUNT_BLKS, 256>>>(W_o1, W_s1, W_o2, W_s2, ei_o, ei_s);
    k_csr<<<98, 1024>>>();
    k_fill_conv<<<COUNT_BLKS + XCONV_BLKS, 256>>>(x_o, ei_o, ei_s);
    k_gemm<<<dim3(GEMM_TILES, 2), 256, GEMM_SMEM>>>(0, a_src_o1, a_src_s1, a_dst_o1, a_dst_s1);
    k_aggregate1<<<dim3(NN / 8, 2), 256>>>(b_o1, b_s1);
    k_gemm<<<dim3(GEMM_TILES, 2), 256, GEMM_SMEM>>>(1, a_src_o2, a_src_s2, a_dst_o2, a_dst_s2);
    k_agg2pred<<<NN / 8, 256>>>(b_o2, b_s2, degree, W_pred, b_pred, out);
}